// round 5
// baseline (speedup 1.0000x reference)
#include <cuda_runtime.h>
#include <cuda_bf16.h>

// ---------------------------------------------------------------------------
// GATModel: 2x (GEMM+scores -> segment-softmax aggregate+BN+ELU) -> final GEMM
// N=50000, E=500000, F=256, H=4 heads, D=64, OUT=64
// R5: f32x2 GEMM, fused score epilogue, atomic segment allocation (no scan).
// ---------------------------------------------------------------------------

#define NMAX 50000
#define EMAX 500000

__device__ float g_buf1[NMAX * 256];
__device__ float g_buf2[NMAX * 256];
__device__ float g_ssrc[NMAX * 4];
__device__ float g_sdst[NMAX * 4];
__device__ int   g_counts[NMAX];
__device__ int   g_rowbeg[NMAX];
__device__ int   g_rowend[NMAX];
__device__ int   g_cursor[NMAX];
__device__ int   g_csrc[EMAX];
__device__ int   g_is64;
__device__ int   g_total;

typedef unsigned long long ull;

// ---------------- f32x2 helpers ----------------
__device__ __forceinline__ ull pk2(float x, float y) {
    ull r;
    asm("mov.b64 %0, {%1,%2};" : "=l"(r) : "f"(x), "f"(y));
    return r;
}
__device__ __forceinline__ ull ffma2(ull a, ull b, ull c) {
    ull d;
    asm("fma.rn.f32x2 %0, %1, %2, %3;" : "=l"(d) : "l"(a), "l"(b), "l"(c));
    return d;
}
__device__ __forceinline__ float2 upk2(ull v) {
    float2 f;
    asm("mov.b64 {%0,%1}, %2;" : "=f"(f.x), "=f"(f.y) : "l"(v));
    return f;
}

// ---------------- edge_index dtype detection ----------------
__global__ void detect_dtype(const void* __restrict__ ei, int N) {
    const long long* p = (const long long*)ei;
    int ok = 1;
    for (int i = 0; i < 16; i++) {
        long long v = p[i];
        if (v < 0 || v >= (long long)N) ok = 0;
    }
    g_is64 = ok;
}

__device__ __forceinline__ int load_idx(const void* ei, long long pos) {
    if (g_is64) return (int)((const long long*)ei)[pos];
    return ((const int*)ei)[pos];
}

// ---------------- CSR build ----------------
__global__ void zero_counts(int N) {
    int i = blockIdx.x * blockDim.x + threadIdx.x;
    if (i < N) g_counts[i] = 0;
    if (i == 0) g_total = 0;
}

__global__ void hist_kernel(const void* __restrict__ ei, int E, int N) {
    int e = blockIdx.x * blockDim.x + threadIdx.x;
    if (e < E) {
        int d = load_idx(ei, (long long)E + e);
        if (d >= 0 && d < N) atomicAdd(&g_counts[d], 1);
    }
}

// Per-block prefix + one atomicAdd: allocates a contiguous segment per node.
// (Segment ORDER across nodes is irrelevant; only grouping matters.)
__global__ void __launch_bounds__(1024)
alloc_rows(int N) {
    __shared__ int sh[1024];
    __shared__ int sbase;
    int tid = threadIdx.x;
    int i = blockIdx.x * 1024 + tid;
    int c = (i < N) ? g_counts[i] : 0;
    sh[tid] = c;
    __syncthreads();
    // Hillis-Steele inclusive scan
    for (int off = 1; off < 1024; off <<= 1) {
        int v = (tid >= off) ? sh[tid - off] : 0;
        __syncthreads();
        sh[tid] += v;
        __syncthreads();
    }
    if (tid == 1023) sbase = atomicAdd(&g_total, sh[1023]);
    __syncthreads();
    if (i < N) {
        int b = sbase + sh[tid] - c;
        g_rowbeg[i] = b;
        g_rowend[i] = b + c;
        g_cursor[i] = b;
    }
}

__global__ void scatter_kernel(const void* __restrict__ ei, int E, int N) {
    int e = blockIdx.x * blockDim.x + threadIdx.x;
    if (e < E) {
        int d = load_idx(ei, (long long)E + e);
        int s = load_idx(ei, e);
        if (d >= 0 && d < N && s >= 0 && s < N) {
            int pos = atomicAdd(&g_cursor[d], 1);
            if (pos >= 0 && pos < E) g_csrc[pos] = s;
        }
    }
}

// ---------------- GEMM: C[M,Nout] = A[M,256]*B[Nout,256]^T (+bias) ----------
// BM=128, BN=64, BK=16; 128 threads: tx=tid&7 (8 cols each), ty=tid>>3 (8 rows).
// f32x2 col-paired accumulators; optional fused attention-score epilogue
// (valid because BN=64 == head width, head = blockIdx.y).
__global__ void __launch_bounds__(128)
gemm_f32x2(const float* __restrict__ Aext, int useBuf2,
           const float* __restrict__ B,
           const float* __restrict__ bias,
           float* __restrict__ Cext, int toExt,
           int M, int Nout,
           const float* __restrict__ a_src, const float* __restrict__ a_dst) {
    const int BM = 128, BK = 16;
    __shared__ float As[BK][BM + 4];   // 132 floats/row (528B, 16B-aligned)
    __shared__ float Bs[BK][64 + 4];   // 68 floats/row  (272B, 16B-aligned)

    const float* A = useBuf2 ? (const float*)g_buf2 : Aext;
    float* C = toExt ? Cext : (float*)g_buf1;

    int tid = threadIdx.x;
    int tx = tid & 7;
    int ty = tid >> 3;
    int row0 = blockIdx.x * BM;
    int col0 = blockIdx.y * 64;

    ull acc[8][4];
#pragma unroll
    for (int i = 0; i < 8; i++)
#pragma unroll
        for (int j = 0; j < 4; j++) acc[i][j] = 0ull;

    const int brow = tid >> 1;          // 0..63
    const int blk  = (tid & 1) * 8;     // 0 or 8

    for (int kt = 0; kt < 256; kt += BK) {
        // stage A: thread tid loads row tid's 16 k-values
        {
            int grow = row0 + tid;
            if (grow < M) {
                const float4* src = (const float4*)&A[(size_t)grow * 256 + kt];
#pragma unroll
                for (int q = 0; q < 4; q++) {
                    float4 v = src[q];
                    As[4 * q + 0][tid] = v.x;
                    As[4 * q + 1][tid] = v.y;
                    As[4 * q + 2][tid] = v.z;
                    As[4 * q + 3][tid] = v.w;
                }
            } else {
#pragma unroll
                for (int q = 0; q < 16; q++) As[q][tid] = 0.f;
            }
        }
        // stage B: pair of threads per row, 8 k-values each
        {
            const float4* src = (const float4*)&B[(size_t)(col0 + brow) * 256 + kt + blk];
#pragma unroll
            for (int q = 0; q < 2; q++) {
                float4 v = src[q];
                Bs[blk + 4 * q + 0][brow] = v.x;
                Bs[blk + 4 * q + 1][brow] = v.y;
                Bs[blk + 4 * q + 2][brow] = v.z;
                Bs[blk + 4 * q + 3][brow] = v.w;
            }
        }
        __syncthreads();
#pragma unroll
        for (int k = 0; k < BK; k++) {
            float4 aA = *(const float4*)&As[k][ty * 8];
            float4 aB = *(const float4*)&As[k][ty * 8 + 4];
            ulonglong2 bv0 = *(const ulonglong2*)&Bs[k][tx * 8];
            ulonglong2 bv1 = *(const ulonglong2*)&Bs[k][tx * 8 + 4];
            float a[8] = {aA.x, aA.y, aA.z, aA.w, aB.x, aB.y, aB.z, aB.w};
#pragma unroll
            for (int i = 0; i < 8; i++) {
                ull ai = pk2(a[i], a[i]);
                acc[i][0] = ffma2(ai, bv0.x, acc[i][0]);
                acc[i][1] = ffma2(ai, bv0.y, acc[i][1]);
                acc[i][2] = ffma2(ai, bv1.x, acc[i][2]);
                acc[i][3] = ffma2(ai, bv1.y, acc[i][3]);
            }
        }
        __syncthreads();
    }

    int c0 = col0 + tx * 8;
    float bb[8];
#pragma unroll
    for (int j = 0; j < 8; j++) bb[j] = bias ? bias[c0 + j] : 0.f;

#pragma unroll
    for (int i = 0; i < 8; i++) {
        int r = row0 + ty * 8 + i;
        float cv[8];
#pragma unroll
        for (int j2 = 0; j2 < 4; j2++) {
            float2 v = upk2(acc[i][j2]);
            cv[2 * j2] = v.x + bb[2 * j2];
            cv[2 * j2 + 1] = v.y + bb[2 * j2 + 1];
        }
        if (r < M) {
            *(float4*)&C[(size_t)r * Nout + c0] = make_float4(cv[0], cv[1], cv[2], cv[3]);
            *(float4*)&C[(size_t)r * Nout + c0 + 4] = make_float4(cv[4], cv[5], cv[6], cv[7]);
        }
        if (a_src) {
            // fused attention scores for head = blockIdx.y
            float vs = 0.f, vd = 0.f;
#pragma unroll
            for (int j = 0; j < 8; j++) {
                vs = fmaf(cv[j], a_src[c0 + j], vs);
                vd = fmaf(cv[j], a_dst[c0 + j], vd);
            }
#pragma unroll
            for (int o = 4; o; o >>= 1) {
                vs += __shfl_xor_sync(~0u, vs, o);
                vd += __shfl_xor_sync(~0u, vd, o);
            }
            if (tx == 0 && r < M) {
                g_ssrc[r * 4 + blockIdx.y] = vs;
                g_sdst[r * 4 + blockIdx.y] = vd;
            }
        }
    }
}

// ---------------- GAT aggregate + BN + ELU ----------------
__global__ void __launch_bounds__(128)
gat_agg(const float* __restrict__ gamma, const float* __restrict__ beta,
        const float* __restrict__ mean, const float* __restrict__ var) {
    int n = blockIdx.x;
    int tid = threadIdx.x;
    int head = tid >> 5;
    int lane = tid & 31;
    int beg = g_rowbeg[n];
    int end = g_rowend[n];
    float sd = g_sdst[n * 4 + head];
    const float* hfeat = g_buf1;

    float m = 0.f;
    for (int i = beg + lane; i < end; i += 32) {
        int s = g_csrc[i];
        float e = g_ssrc[s * 4 + head] + sd;
        e = (e >= 0.f) ? e : 0.2f * e;
        m = fmaxf(m, e);
    }
#pragma unroll
    for (int o = 16; o; o >>= 1) m = fmaxf(m, __shfl_xor_sync(~0u, m, o));

    float acc0 = 0.f, acc1 = 0.f, ws = 0.f;
    int c = tid * 2;
    for (int i = beg; i < end; i++) {
        int s = g_csrc[i];
        float e = g_ssrc[s * 4 + head] + sd;
        e = (e >= 0.f) ? e : 0.2f * e;
        float wgt = __expf(e - m);
        ws += wgt;
        float2 hv = *(const float2*)&hfeat[(size_t)s * 256 + c];
        acc0 = fmaf(wgt, hv.x, acc0);
        acc1 = fmaf(wgt, hv.y, acc1);
    }
    float inv = 1.f / fmaxf(ws, 1e-9f);
    float o0 = acc0 * inv;
    float o1 = acc1 * inv;

    o0 = (o0 - mean[c]) * rsqrtf(var[c] + 1e-5f) * gamma[c] + beta[c];
    o1 = (o1 - mean[c + 1]) * rsqrtf(var[c + 1] + 1e-5f) * gamma[c + 1] + beta[c + 1];
    o0 = (o0 > 0.f) ? o0 : expm1f(o0);
    o1 = (o1 > 0.f) ? o1 : expm1f(o1);
    *(float2*)&g_buf2[(size_t)n * 256 + c] = make_float2(o0, o1);
}

// ---------------------------------------------------------------------------
extern "C" void kernel_launch(void* const* d_in, const int* in_sizes, int n_in,
                              void* d_out, int out_size) {
    const float* x   = (const float*)d_in[0];
    const void*  ei  = d_in[1];
    const float* W1  = (const float*)d_in[2];
    const float* as1 = (const float*)d_in[3];
    const float* ad1 = (const float*)d_in[4];
    const float* g1  = (const float*)d_in[5];
    const float* b1  = (const float*)d_in[6];
    const float* m1  = (const float*)d_in[7];
    const float* v1  = (const float*)d_in[8];
    const float* W2  = (const float*)d_in[9];
    const float* as2 = (const float*)d_in[10];
    const float* ad2 = (const float*)d_in[11];
    const float* g2  = (const float*)d_in[12];
    const float* b2  = (const float*)d_in[13];
    const float* m2  = (const float*)d_in[14];
    const float* v2  = (const float*)d_in[15];
    const float* Wc  = (const float*)d_in[16];
    const float* bc  = (const float*)d_in[17];
    float* out = (float*)d_out;

    int N = in_sizes[0] / 256;
    int E = in_sizes[1] / 2;

    detect_dtype<<<1, 1>>>(ei, N);
    zero_counts<<<(N + 255) / 256, 256>>>(N);
    hist_kernel<<<(E + 255) / 256, 256>>>(ei, E, N);
    alloc_rows<<<(N + 1023) / 1024, 1024>>>(N);
    scatter_kernel<<<(E + 255) / 256, 256>>>(ei, E, N);

    dim3 gemm_grid((N + 127) / 128, 4);
    dim3 gemm_grid_c((N + 127) / 128, 1);

    // --- layer 1 ---
    gemm_f32x2<<<gemm_grid, 128>>>(x, 0, W1, nullptr, nullptr, 0, N, 256, as1, ad1);
    gat_agg<<<N, 128>>>(g1, b1, m1, v1);

    // --- layer 2 ---
    gemm_f32x2<<<gemm_grid, 128>>>(nullptr, 1, W2, nullptr, nullptr, 0, N, 256, as2, ad2);
    gat_agg<<<N, 128>>>(g2, b2, m2, v2);

    // --- classifier ---
    gemm_f32x2<<<gemm_grid_c, 128>>>(nullptr, 1, Wc, bc, out, 1, N, 64, nullptr, nullptr);
}

// round 6
// speedup vs baseline: 1.9024x; 1.9024x over previous
#include <cuda_runtime.h>
#include <cuda_bf16.h>

// ---------------------------------------------------------------------------
// GATModel: 2x (GEMM+scores -> segment-softmax aggregate+BN+ELU) -> final GEMM
// N=50000, E=500000, F=256, H=4 heads, D=64, OUT=64
// R6: revert GEMM to the proven R4 scalar-FFMA version; keep alloc_rows and
//     fuse the attention-score epilogue into the GEMM.
// ---------------------------------------------------------------------------

#define NMAX 50000
#define EMAX 500000

__device__ float g_buf1[NMAX * 256];
__device__ float g_buf2[NMAX * 256];
__device__ float g_ssrc[NMAX * 4];
__device__ float g_sdst[NMAX * 4];
__device__ int   g_counts[NMAX];
__device__ int   g_rowbeg[NMAX];
__device__ int   g_rowend[NMAX];
__device__ int   g_cursor[NMAX];
__device__ int   g_csrc[EMAX];
__device__ int   g_is64;
__device__ int   g_total;

// ---------------- edge_index dtype detection ----------------
__global__ void detect_dtype(const void* __restrict__ ei, int N) {
    const long long* p = (const long long*)ei;
    int ok = 1;
    for (int i = 0; i < 16; i++) {
        long long v = p[i];
        if (v < 0 || v >= (long long)N) ok = 0;
    }
    g_is64 = ok;
}

__device__ __forceinline__ int load_idx(const void* ei, long long pos) {
    if (g_is64) return (int)((const long long*)ei)[pos];
    return ((const int*)ei)[pos];
}

// ---------------- CSR build ----------------
__global__ void zero_counts(int N) {
    int i = blockIdx.x * blockDim.x + threadIdx.x;
    if (i < N) g_counts[i] = 0;
    if (i == 0) g_total = 0;
}

__global__ void hist_kernel(const void* __restrict__ ei, int E, int N) {
    int e = blockIdx.x * blockDim.x + threadIdx.x;
    if (e < E) {
        int d = load_idx(ei, (long long)E + e);
        if (d >= 0 && d < N) atomicAdd(&g_counts[d], 1);
    }
}

// Per-block prefix + one atomicAdd segment allocation (order irrelevant).
__global__ void __launch_bounds__(1024)
alloc_rows(int N) {
    __shared__ int sh[1024];
    __shared__ int sbase;
    int tid = threadIdx.x;
    int i = blockIdx.x * 1024 + tid;
    int c = (i < N) ? g_counts[i] : 0;
    sh[tid] = c;
    __syncthreads();
    for (int off = 1; off < 1024; off <<= 1) {
        int v = (tid >= off) ? sh[tid - off] : 0;
        __syncthreads();
        sh[tid] += v;
        __syncthreads();
    }
    if (tid == 1023) sbase = atomicAdd(&g_total, sh[1023]);
    __syncthreads();
    if (i < N) {
        int b = sbase + sh[tid] - c;
        g_rowbeg[i] = b;
        g_rowend[i] = b + c;
        g_cursor[i] = b;
    }
}

__global__ void scatter_kernel(const void* __restrict__ ei, int E, int N) {
    int e = blockIdx.x * blockDim.x + threadIdx.x;
    if (e < E) {
        int d = load_idx(ei, (long long)E + e);
        int s = load_idx(ei, e);
        if (d >= 0 && d < N && s >= 0 && s < N) {
            int pos = atomicAdd(&g_cursor[d], 1);
            if (pos >= 0 && pos < E) g_csrc[pos] = s;
        }
    }
}

// ---------------- GEMM: C[M,Nout] = A[M,256]*B[Nout,256]^T (+bias) ----------
// BM=128, BN=64, BK=16, 256 threads (16x16), TM=8, TN=4, scalar FFMA.
// Optional fused attention-score epilogue (BN=64 == head width; head=blockIdx.y).
__global__ void __launch_bounds__(256)
gemm_tn(const float* __restrict__ Aext, int useBuf2,
        const float* __restrict__ B,
        const float* __restrict__ bias,
        float* __restrict__ Cext, int toExt,
        int M, int Nout,
        const float* __restrict__ a_src, const float* __restrict__ a_dst) {
    const int BM = 128, BN = 64, BK = 16, TM = 8;
    __shared__ float As[BK][BM + 4];
    __shared__ float Bs[BK][BN + 4];

    const float* A = useBuf2 ? (const float*)g_buf2 : Aext;
    float* C = toExt ? Cext : (float*)g_buf1;

    int tid = threadIdx.x;
    int tx = tid & 15;
    int ty = tid >> 4;
    int row0 = blockIdx.x * BM;
    int col0 = blockIdx.y * BN;

    float acc[TM][4];
#pragma unroll
    for (int i = 0; i < TM; i++)
#pragma unroll
        for (int j = 0; j < 4; j++) acc[i][j] = 0.f;

    const int lr = tid >> 2;          // 0..63
    const int lk = (tid & 3) * 4;     // 0,4,8,12

    for (int kt = 0; kt < 256; kt += BK) {
#pragma unroll
        for (int h = 0; h < 2; h++) {
            int r = lr + h * 64;
            int grow = row0 + r;
            float4 v = make_float4(0.f, 0.f, 0.f, 0.f);
            if (grow < M) v = *(const float4*)&A[(size_t)grow * 256 + kt + lk];
            As[lk + 0][r] = v.x;
            As[lk + 1][r] = v.y;
            As[lk + 2][r] = v.z;
            As[lk + 3][r] = v.w;
        }
        {
            int r = lr;
            float4 v = *(const float4*)&B[(size_t)(col0 + r) * 256 + kt + lk];
            Bs[lk + 0][r] = v.x;
            Bs[lk + 1][r] = v.y;
            Bs[lk + 2][r] = v.z;
            Bs[lk + 3][r] = v.w;
        }
        __syncthreads();
#pragma unroll
        for (int k = 0; k < BK; k++) {
            float a[TM], b[4];
            *(float4*)&a[0] = *(const float4*)&As[k][ty * TM];
            *(float4*)&a[4] = *(const float4*)&As[k][ty * TM + 4];
            *(float4*)&b[0] = *(const float4*)&Bs[k][tx * 4];
#pragma unroll
            for (int i = 0; i < TM; i++) {
#pragma unroll
                for (int j = 0; j < 4; j++)
                    acc[i][j] = fmaf(a[i], b[j], acc[i][j]);
            }
        }
        __syncthreads();
    }

    int c = col0 + tx * 4;
    float bx = 0.f, by = 0.f, bz = 0.f, bw = 0.f;
    if (bias) {
        bx = bias[c]; by = bias[c + 1]; bz = bias[c + 2]; bw = bias[c + 3];
    }
    // preload attention weights for this thread's 4 columns (if fusing scores)
    float w_s[4] = {0.f, 0.f, 0.f, 0.f}, w_d[4] = {0.f, 0.f, 0.f, 0.f};
    if (a_src) {
#pragma unroll
        for (int j = 0; j < 4; j++) {
            w_s[j] = a_src[c + j];
            w_d[j] = a_dst[c + j];
        }
    }
#pragma unroll
    for (int i = 0; i < TM; i++) {
        int r = row0 + ty * TM + i;
        float v0 = acc[i][0] + bx, v1 = acc[i][1] + by;
        float v2 = acc[i][2] + bz, v3 = acc[i][3] + bw;
        if (r < M) {
            *(float4*)&C[(size_t)r * Nout + c] = make_float4(v0, v1, v2, v3);
        }
        if (a_src) {
            // fused attention scores for head = blockIdx.y; reduce across the
            // 16 tx lanes (contiguous within a warp: lanes ty%2*16 .. +15).
            float vs = v0 * w_s[0] + v1 * w_s[1] + v2 * w_s[2] + v3 * w_s[3];
            float vd = v0 * w_d[0] + v1 * w_d[1] + v2 * w_d[2] + v3 * w_d[3];
#pragma unroll
            for (int o = 8; o; o >>= 1) {
                vs += __shfl_xor_sync(~0u, vs, o);
                vd += __shfl_xor_sync(~0u, vd, o);
            }
            if (tx == 0 && r < M) {
                g_ssrc[r * 4 + blockIdx.y] = vs;
                g_sdst[r * 4 + blockIdx.y] = vd;
            }
        }
    }
}

// ---------------- GAT aggregate + BN + ELU ----------------
__global__ void __launch_bounds__(128)
gat_agg(const float* __restrict__ gamma, const float* __restrict__ beta,
        const float* __restrict__ mean, const float* __restrict__ var) {
    int n = blockIdx.x;
    int tid = threadIdx.x;
    int head = tid >> 5;
    int lane = tid & 31;
    int beg = g_rowbeg[n];
    int end = g_rowend[n];
    float sd = g_sdst[n * 4 + head];
    const float* hfeat = g_buf1;

    float m = 0.f;
    for (int i = beg + lane; i < end; i += 32) {
        int s = g_csrc[i];
        float e = g_ssrc[s * 4 + head] + sd;
        e = (e >= 0.f) ? e : 0.2f * e;
        m = fmaxf(m, e);
    }
#pragma unroll
    for (int o = 16; o; o >>= 1) m = fmaxf(m, __shfl_xor_sync(~0u, m, o));

    float acc0 = 0.f, acc1 = 0.f, ws = 0.f;
    int c = tid * 2;
    for (int i = beg; i < end; i++) {
        int s = g_csrc[i];
        float e = g_ssrc[s * 4 + head] + sd;
        e = (e >= 0.f) ? e : 0.2f * e;
        float wgt = __expf(e - m);
        ws += wgt;
        float2 hv = *(const float2*)&hfeat[(size_t)s * 256 + c];
        acc0 = fmaf(wgt, hv.x, acc0);
        acc1 = fmaf(wgt, hv.y, acc1);
    }
    float inv = 1.f / fmaxf(ws, 1e-9f);
    float o0 = acc0 * inv;
    float o1 = acc1 * inv;

    o0 = (o0 - mean[c]) * rsqrtf(var[c] + 1e-5f) * gamma[c] + beta[c];
    o1 = (o1 - mean[c + 1]) * rsqrtf(var[c + 1] + 1e-5f) * gamma[c + 1] + beta[c + 1];
    o0 = (o0 > 0.f) ? o0 : expm1f(o0);
    o1 = (o1 > 0.f) ? o1 : expm1f(o1);
    *(float2*)&g_buf2[(size_t)n * 256 + c] = make_float2(o0, o1);
}

// ---------------------------------------------------------------------------
extern "C" void kernel_launch(void* const* d_in, const int* in_sizes, int n_in,
                              void* d_out, int out_size) {
    const float* x   = (const float*)d_in[0];
    const void*  ei  = d_in[1];
    const float* W1  = (const float*)d_in[2];
    const float* as1 = (const float*)d_in[3];
    const float* ad1 = (const float*)d_in[4];
    const float* g1  = (const float*)d_in[5];
    const float* b1  = (const float*)d_in[6];
    const float* m1  = (const float*)d_in[7];
    const float* v1  = (const float*)d_in[8];
    const float* W2  = (const float*)d_in[9];
    const float* as2 = (const float*)d_in[10];
    const float* ad2 = (const float*)d_in[11];
    const float* g2  = (const float*)d_in[12];
    const float* b2  = (const float*)d_in[13];
    const float* m2  = (const float*)d_in[14];
    const float* v2  = (const float*)d_in[15];
    const float* Wc  = (const float*)d_in[16];
    const float* bc  = (const float*)d_in[17];
    float* out = (float*)d_out;

    int N = in_sizes[0] / 256;
    int E = in_sizes[1] / 2;

    detect_dtype<<<1, 1>>>(ei, N);
    zero_counts<<<(N + 255) / 256, 256>>>(N);
    hist_kernel<<<(E + 255) / 256, 256>>>(ei, E, N);
    alloc_rows<<<(N + 1023) / 1024, 1024>>>(N);
    scatter_kernel<<<(E + 255) / 256, 256>>>(ei, E, N);

    dim3 gemm_grid((N + 127) / 128, 4);
    dim3 gemm_grid_c((N + 127) / 128, 1);

    // --- layer 1 ---
    gemm_tn<<<gemm_grid, 256>>>(x, 0, W1, nullptr, nullptr, 0, N, 256, as1, ad1);
    gat_agg<<<N, 128>>>(g1, b1, m1, v1);

    // --- layer 2 ---
    gemm_tn<<<gemm_grid, 256>>>(nullptr, 1, W2, nullptr, nullptr, 0, N, 256, as2, ad2);
    gat_agg<<<N, 128>>>(g2, b2, m2, v2);

    // --- classifier ---
    gemm_tn<<<gemm_grid_c, 256>>>(nullptr, 1, Wc, bc, out, 1, N, 64, nullptr, nullptr);
}

// round 8
// speedup vs baseline: 1.9242x; 1.0114x over previous
#include <cuda_runtime.h>
#include <cuda_bf16.h>
#include <cstdint>

// ---------------------------------------------------------------------------
// GATModel on GB300: tcgen05 bf16 split-GEMM (3-term: hh + hl + lh)
// 2x (GEMM+scores -> segment-softmax aggregate+BN+ELU) -> classifier GEMM
// N=50000, E=500000, F=256, H=4, D=64, OUT=64
// R8: gate tcgen05 code on arch-specific feature macros so the harness's
//     generic compute_103 PTX pass compiles (tcgen05 is 'a'-suffix only).
// ---------------------------------------------------------------------------

#if defined(__CUDA_ARCH_FEAT_SM103_ALL) || defined(__CUDA_ARCH_FEAT_SM100_ALL) || \
    defined(__CUDA_ARCH_FEAT_SM101_ALL) || defined(__CUDA_ARCH_SPECIFIC__)
#define TC_OK 1
#else
#define TC_OK 0
#endif

#define NMAX 50000
#define EMAX 500000

__device__ float          g_buf1[NMAX * 256];   // GEMM output h (fp32)
__device__ __nv_bfloat16  g_a_hi[NMAX * 256];   // GEMM A input, hi part
__device__ __nv_bfloat16  g_a_lo[NMAX * 256];   // GEMM A input, lo part
__device__ __nv_bfloat16  g_wb_hi[256 * 256];   // weight B, hi
__device__ __nv_bfloat16  g_wb_lo[256 * 256];   // weight B, lo
__device__ float g_ssrc[NMAX * 4];
__device__ float g_sdst[NMAX * 4];
__device__ int   g_counts[NMAX];
__device__ int   g_rowbeg[NMAX];
__device__ int   g_rowend[NMAX];
__device__ int   g_cursor[NMAX];
__device__ int   g_csrc[EMAX];
__device__ int   g_is64;
__device__ int   g_total;

// ---------------- edge_index dtype detection ----------------
__global__ void detect_dtype(const void* __restrict__ ei, int N) {
    const long long* p = (const long long*)ei;
    int ok = 1;
    for (int i = 0; i < 16; i++) {
        long long v = p[i];
        if (v < 0 || v >= (long long)N) ok = 0;
    }
    g_is64 = ok;
}
__device__ __forceinline__ int load_idx(const void* ei, long long pos) {
    if (g_is64) return (int)((const long long*)ei)[pos];
    return ((const int*)ei)[pos];
}

// ---------------- CSR build ----------------
__global__ void zero_counts(int N) {
    int i = blockIdx.x * blockDim.x + threadIdx.x;
    if (i < N) g_counts[i] = 0;
    if (i == 0) g_total = 0;
}
__global__ void hist_kernel(const void* __restrict__ ei, int E, int N) {
    int e = blockIdx.x * blockDim.x + threadIdx.x;
    if (e < E) {
        int d = load_idx(ei, (long long)E + e);
        if (d >= 0 && d < N) atomicAdd(&g_counts[d], 1);
    }
}
__global__ void __launch_bounds__(1024)
alloc_rows(int N) {
    __shared__ int sh[1024];
    __shared__ int sbase;
    int tid = threadIdx.x;
    int i = blockIdx.x * 1024 + tid;
    int c = (i < N) ? g_counts[i] : 0;
    sh[tid] = c;
    __syncthreads();
    for (int off = 1; off < 1024; off <<= 1) {
        int v = (tid >= off) ? sh[tid - off] : 0;
        __syncthreads();
        sh[tid] += v;
        __syncthreads();
    }
    if (tid == 1023) sbase = atomicAdd(&g_total, sh[1023]);
    __syncthreads();
    if (i < N) {
        int b = sbase + sh[tid] - c;
        g_rowbeg[i] = b;
        g_rowend[i] = b + c;
        g_cursor[i] = b;
    }
}
__global__ void scatter_kernel(const void* __restrict__ ei, int E, int N) {
    int e = blockIdx.x * blockDim.x + threadIdx.x;
    if (e < E) {
        int d = load_idx(ei, (long long)E + e);
        int s = load_idx(ei, e);
        if (d >= 0 && d < N && s >= 0 && s < N) {
            int pos = atomicAdd(&g_cursor[d], 1);
            if (pos >= 0 && pos < E) g_csrc[pos] = s;
        }
    }
}

// ---------------- fp32 -> bf16 hi/lo split conversions ----------------
__global__ void conv_split_x(const float* __restrict__ src, int n2) {
    int i = blockIdx.x * blockDim.x + threadIdx.x;
    if (i < n2) {
        float2 v = ((const float2*)src)[i];
        __nv_bfloat16 h0 = __float2bfloat16(v.x);
        __nv_bfloat16 h1 = __float2bfloat16(v.y);
        ((__nv_bfloat162*)g_a_hi)[i] = __halves2bfloat162(h0, h1);
        ((__nv_bfloat162*)g_a_lo)[i] = __halves2bfloat162(
            __float2bfloat16(v.x - __bfloat162float(h0)),
            __float2bfloat16(v.y - __bfloat162float(h1)));
    }
}
__global__ void conv_split_w(const float* __restrict__ src, int n2) {
    int i = blockIdx.x * blockDim.x + threadIdx.x;
    if (i < n2) {
        float2 v = ((const float2*)src)[i];
        __nv_bfloat16 h0 = __float2bfloat16(v.x);
        __nv_bfloat16 h1 = __float2bfloat16(v.y);
        ((__nv_bfloat162*)g_wb_hi)[i] = __halves2bfloat162(h0, h1);
        ((__nv_bfloat162*)g_wb_lo)[i] = __halves2bfloat162(
            __float2bfloat16(v.x - __bfloat162float(h0)),
            __float2bfloat16(v.y - __bfloat162float(h1)));
    }
}

// ---------------- tcgen05 helpers (only in arch-specific pass) ----------------
#if TC_OK
__device__ __forceinline__ uint32_t elect_one_pred() {
    uint32_t pred;
    asm volatile("{\n\t.reg .pred p;\n\telect.sync _|p, 0xFFFFFFFF;\n\t"
                 "selp.b32 %0, 1, 0, p;\n\t}" : "=r"(pred));
    return pred;
}
__device__ __forceinline__ uint32_t smem_to_u32(const void* p) {
    uint32_t a;
    asm("{ .reg .u64 t; cvta.to.shared.u64 t, %1; cvt.u32.u64 %0, t; }"
        : "=r"(a) : "l"(p));
    return a;
}
#define MBARRIER_INIT(mbar, count) \
    asm volatile("mbarrier.init.shared.b64 [%0], %1;" \
                 :: "r"((uint32_t)(mbar)), "r"((uint32_t)(count)) : "memory")
#define MBARRIER_WAIT_PARITY(mbar, parity) do { \
    uint32_t _m = (uint32_t)(mbar), _p = (uint32_t)(parity), _d; \
    asm volatile("{\n\t.reg .pred p;\n\t" \
        "mbarrier.try_wait.parity.acquire.cta.shared::cta.b64 p, [%1], %2;\n\t" \
        "selp.b32 %0, 1, 0, p;\n\t}" : "=r"(_d) : "r"(_m), "r"(_p) : "memory"); \
    if (!_d) { \
        asm volatile("{\n\t.reg .pred P1;\n\t" \
            "WL_%=:\n\t" \
            "mbarrier.try_wait.parity.acquire.cta.shared::cta.b64 P1, [%0], %1, 0x989680;\n\t" \
            "@P1 bra.uni WD_%=;\n\tbra.uni WL_%=;\n\tWD_%=:\n\t}" \
            :: "r"(_m), "r"(_p) : "memory"); \
    } \
} while (0)
#define TCGEN05_ALLOC(sr, n) \
    asm volatile("tcgen05.alloc.cta_group::1.sync.aligned.shared::cta.b32 [%0], %1;" \
                 :: "r"((uint32_t)(sr)), "r"((uint32_t)(n)) : "memory")
#define TCGEN05_DEALLOC(t, n) \
    asm volatile("tcgen05.dealloc.cta_group::1.sync.aligned.b32 %0, %1;" \
                 :: "r"(t), "r"((uint32_t)(n)))
#define TCGEN05_RELINQ() \
    asm volatile("tcgen05.relinquish_alloc_permit.cta_group::1.sync.aligned;")
#define TCGEN05_COMMIT(mbar) \
    asm volatile("tcgen05.commit.cta_group::1.mbarrier::arrive::one.shared::cluster.b64 [%0];" \
                 :: "r"((uint32_t)(mbar)) : "memory")
#define TCGEN05_FENCE_AFTER() \
    asm volatile("tcgen05.fence::after_thread_sync;" ::: "memory")
#define TCGEN05_WAIT_LD() \
    asm volatile("tcgen05.wait::ld.sync.aligned;" ::: "memory")
#define TCGEN05_LD_32X32B_X32(r, ta) \
    asm volatile("tcgen05.ld.sync.aligned.32x32b.x32.b32 " \
        "{%0, %1, %2, %3, %4, %5, %6, %7, %8, %9, %10, %11, %12, %13, %14, %15, " \
        " %16, %17, %18, %19, %20, %21, %22, %23, %24, %25, %26, %27, %28, %29, %30, %31}, [%32];" \
        : "=r"((r)[0]), "=r"((r)[1]), "=r"((r)[2]), "=r"((r)[3]), \
          "=r"((r)[4]), "=r"((r)[5]), "=r"((r)[6]), "=r"((r)[7]), \
          "=r"((r)[8]), "=r"((r)[9]), "=r"((r)[10]), "=r"((r)[11]), \
          "=r"((r)[12]), "=r"((r)[13]), "=r"((r)[14]), "=r"((r)[15]), \
          "=r"((r)[16]), "=r"((r)[17]), "=r"((r)[18]), "=r"((r)[19]), \
          "=r"((r)[20]), "=r"((r)[21]), "=r"((r)[22]), "=r"((r)[23]), \
          "=r"((r)[24]), "=r"((r)[25]), "=r"((r)[26]), "=r"((r)[27]), \
          "=r"((r)[28]), "=r"((r)[29]), "=r"((r)[30]), "=r"((r)[31]) \
        : "r"(ta))

// SW128 K-major smem descriptor: layout=2, version=1, SBO=64, LBO=1
__device__ __forceinline__ uint64_t make_desc(uint32_t addr) {
    uint64_t base = (uint64_t(2) << 61) | (uint64_t(1) << 46) |
                    (uint64_t(64) << 32) | (uint64_t(1) << 16);
    return base | ((uint64_t)(addr >> 4) & 0x3FFF);
}
// SS-mode cg1 bf16 MMA, f32 accum
__device__ __forceinline__ void mma_f16_ss(uint32_t d, uint64_t ad, uint64_t bd,
                                           uint32_t idesc, bool en) {
    uint32_t e = en ? 1u : 0u;
    asm volatile("{\n\t.reg .pred p;\n\tsetp.ne.u32 p, %5, 0;\n\t"
                 "tcgen05.mma.cta_group::1.kind::f16 [%0], %1, %2, %3, {%4, %4, %4, %4}, p;\n\t}"
                 :: "r"(d), "l"(ad), "l"(bd), "r"(idesc), "r"(0u), "r"(e)
                 : "memory");
}
// idesc: dtype=F32(1<<4), atype=BF16(1<<7), btype=BF16(1<<10), N=64(8<<17), M=128(8<<24)
#define MMA_IDESC 0x8100490u
#endif  // TC_OK

// ---------------- tcgen05 split-GEMM ----------------
// Per CTA: C[128 rows, 64 cols] = A[128,256] * B[64,256]^T with A,B in hi/lo
// bf16 split (3 accumulated MMA terms). Epilogue: fp32 C (+bias) and optional
// fused attention scores (col block == head).
#define SM_TMEM 0
#define SM_MBAR 8
#define SM_A_HI 1024
#define SM_A_LO (1024 + 65536)
#define SM_B_HI (1024 + 131072)
#define SM_B_LO (1024 + 163840)
#define SM_TOTAL (1024 + 196608)

__global__ void __launch_bounds__(256)
gemm_tc(const float* __restrict__ bias,
        float* __restrict__ Cext, int toExt, int M, int Nout,
        const float* __restrict__ a_src, const float* __restrict__ a_dst) {
#if TC_OK
    extern __shared__ char smem[];
    uint32_t sb = smem_to_u32(smem);
    int tid = threadIdx.x;
    int wid = tid >> 5;
    int lane = tid & 31;
    int row0 = blockIdx.x * 128;
    int col0 = blockIdx.y * 64;
    float* C = toExt ? Cext : (float*)g_buf1;

    if (wid == 0) {
        TCGEN05_ALLOC(sb + SM_TMEM, 128);
        TCGEN05_RELINQ();
    }
    if (tid == 0) MBARRIER_INIT(sb + SM_MBAR, 1);
    __syncthreads();
    uint32_t tmem;
    asm volatile("ld.shared.b32 %0, [%1];" : "=r"(tmem) : "r"(sb + SM_TMEM));

    // ---- load A tiles (hi: threads 0-127 row t; lo: threads 128-255) ----
    {
        int r = tid & 127;
        const __nv_bfloat16* srcA = (tid < 128) ? g_a_hi : g_a_lo;
        int base = (tid < 128) ? SM_A_HI : SM_A_LO;
        int grow = row0 + r;
        const uint4* src = (const uint4*)(srcA + (size_t)grow * 256);
        int arow = r >> 3, irow = r & 7;
#pragma unroll
        for (int c = 0; c < 32; c++) {
            uint4 v = (grow < M) ? src[c] : make_uint4(0u, 0u, 0u, 0u);
            int off = (arow + (c >> 3) * 16) * 1024 + irow * 128 + (c & 7) * 16;
            off ^= (off >> 3) & 0x70;
            *(uint4*)(smem + base + off) = v;
        }
    }
    // ---- load B tiles (128 rowbufs: 64 hi + 64 lo; 2 threads per rowbuf) --
    {
        int rb = tid >> 1;
        int r = rb & 63;
        const __nv_bfloat16* srcB = (rb < 64) ? g_wb_hi : g_wb_lo;
        int base = (rb < 64) ? SM_B_HI : SM_B_LO;
        const uint4* src = (const uint4*)(srcB + (size_t)(col0 + r) * 256);
        int arow = r >> 3, irow = r & 7;
        int cs = (tid & 1) * 16;
#pragma unroll
        for (int q = 0; q < 16; q++) {
            int c = cs + q;
            uint4 v = src[c];
            int off = (arow + (c >> 3) * 8) * 1024 + irow * 128 + (c & 7) * 16;
            off ^= (off >> 3) & 0x70;
            *(uint4*)(smem + base + off) = v;
        }
    }
    __syncthreads();
    asm volatile("fence.proxy.async.shared::cta;" ::: "memory");

    // ---- issue 3x16 MMAs (hh, hl, lh) ----
    if (wid == 0) {
        if (elect_one_pred()) {
            uint64_t dA_hi = make_desc(sb + SM_A_HI);
            uint64_t dA_lo = make_desc(sb + SM_A_LO);
            uint64_t dB_hi = make_desc(sb + SM_B_HI);
            uint64_t dB_lo = make_desc(sb + SM_B_LO);
#pragma unroll
            for (int term = 0; term < 3; term++) {
                uint64_t da = (term == 2) ? dA_lo : dA_hi;
                uint64_t db = (term == 1) ? dB_lo : dB_hi;
#pragma unroll
                for (int kc = 0; kc < 16; kc++) {
                    uint64_t offA = (uint64_t)((kc >> 2) * 1024 + (kc & 3) * 2);
                    uint64_t offB = (uint64_t)((kc >> 2) * 512 + (kc & 3) * 2);
                    mma_f16_ss(tmem, da + offA, db + offB, MMA_IDESC,
                               !(term == 0 && kc == 0));
                }
            }
            TCGEN05_COMMIT(sb + SM_MBAR);
        }
    }

    MBARRIER_WAIT_PARITY(sb + SM_MBAR, 0);
    TCGEN05_FENCE_AFTER();

    // ---- epilogue: warps 0-3 read D rows (wid*32+lane), full 64 cols ----
    if (wid < 4) {
        uint32_t d0[32], d1[32];
        TCGEN05_LD_32X32B_X32(d0, tmem);
        TCGEN05_LD_32X32B_X32(d1, tmem + 32);
        TCGEN05_WAIT_LD();
        int r = row0 + wid * 32 + lane;
        if (r < M) {
            float cv[64];
#pragma unroll
            for (int j = 0; j < 32; j++) {
                cv[j] = __uint_as_float(d0[j]);
                cv[32 + j] = __uint_as_float(d1[j]);
            }
            if (bias) {
#pragma unroll
                for (int j = 0; j < 64; j++) cv[j] += bias[col0 + j];
            }
            float* crow = C + (size_t)r * Nout + col0;
#pragma unroll
            for (int q = 0; q < 16; q++) {
                *(float4*)(crow + q * 4) =
                    make_float4(cv[4 * q], cv[4 * q + 1], cv[4 * q + 2], cv[4 * q + 3]);
            }
            if (a_src) {
                float vs = 0.f, vd = 0.f;
#pragma unroll
                for (int j = 0; j < 64; j++) {
                    vs = fmaf(cv[j], a_src[col0 + j], vs);
                    vd = fmaf(cv[j], a_dst[col0 + j], vd);
                }
                g_ssrc[r * 4 + blockIdx.y] = vs;
                g_sdst[r * 4 + blockIdx.y] = vd;
            }
        }
    }
    __syncthreads();
    if (tid == 0)
        asm volatile("mbarrier.inval.shared.b64 [%0];" :: "r"(sb + SM_MBAR) : "memory");
    if (wid == 0) TCGEN05_DEALLOC(tmem, 128);
#endif  // TC_OK
}

// ---------------- GAT aggregate + BN + ELU (emits bf16 hi/lo) ----------------
__global__ void __launch_bounds__(128)
gat_agg(const float* __restrict__ gamma, const float* __restrict__ beta,
        const float* __restrict__ mean, const float* __restrict__ var) {
    int n = blockIdx.x;
    int tid = threadIdx.x;
    int head = tid >> 5;
    int lane = tid & 31;
    int beg = g_rowbeg[n];
    int end = g_rowend[n];
    float sd = g_sdst[n * 4 + head];
    const float* hfeat = g_buf1;

    float m = 0.f;
    for (int i = beg + lane; i < end; i += 32) {
        int s = g_csrc[i];
        float e = g_ssrc[s * 4 + head] + sd;
        e = (e >= 0.f) ? e : 0.2f * e;
        m = fmaxf(m, e);
    }
#pragma unroll
    for (int o = 16; o; o >>= 1) m = fmaxf(m, __shfl_xor_sync(~0u, m, o));

    float acc0 = 0.f, acc1 = 0.f, ws = 0.f;
    int c = tid * 2;
    for (int i = beg; i < end; i++) {
        int s = g_csrc[i];
        float e = g_ssrc[s * 4 + head] + sd;
        e = (e >= 0.f) ? e : 0.2f * e;
        float wgt = __expf(e - m);
        ws += wgt;
        float2 hv = *(const float2*)&hfeat[(size_t)s * 256 + c];
        acc0 = fmaf(wgt, hv.x, acc0);
        acc1 = fmaf(wgt, hv.y, acc1);
    }
    float inv = 1.f / fmaxf(ws, 1e-9f);
    float o0 = acc0 * inv;
    float o1 = acc1 * inv;

    o0 = (o0 - mean[c]) * rsqrtf(var[c] + 1e-5f) * gamma[c] + beta[c];
    o1 = (o1 - mean[c + 1]) * rsqrtf(var[c + 1] + 1e-5f) * gamma[c + 1] + beta[c + 1];
    o0 = (o0 > 0.f) ? o0 : expm1f(o0);
    o1 = (o1 > 0.f) ? o1 : expm1f(o1);

    // emit bf16 hi/lo split for the next GEMM's A operand
    __nv_bfloat16 h0 = __float2bfloat16(o0);
    __nv_bfloat16 h1 = __float2bfloat16(o1);
    size_t idx2 = ((size_t)n * 256 + c) >> 1;
    ((__nv_bfloat162*)g_a_hi)[idx2] = __halves2bfloat162(h0, h1);
    ((__nv_bfloat162*)g_a_lo)[idx2] = __halves2bfloat162(
        __float2bfloat16(o0 - __bfloat162float(h0)),
        __float2bfloat16(o1 - __bfloat162float(h1)));
}

// ---------------------------------------------------------------------------
extern "C" void kernel_launch(void* const* d_in, const int* in_sizes, int n_in,
                              void* d_out, int out_size) {
    const float* x   = (const float*)d_in[0];
    const void*  ei  = d_in[1];
    const float* W1  = (const float*)d_in[2];
    const float* as1 = (const float*)d_in[3];
    const float* ad1 = (const float*)d_in[4];
    const float* g1  = (const float*)d_in[5];
    const float* b1  = (const float*)d_in[6];
    const float* m1  = (const float*)d_in[7];
    const float* v1  = (const float*)d_in[8];
    const float* W2  = (const float*)d_in[9];
    const float* as2 = (const float*)d_in[10];
    const float* ad2 = (const float*)d_in[11];
    const float* g2  = (const float*)d_in[12];
    const float* b2  = (const float*)d_in[13];
    const float* m2  = (const float*)d_in[14];
    const float* v2  = (const float*)d_in[15];
    const float* Wc  = (const float*)d_in[16];
    const float* bc  = (const float*)d_in[17];
    float* out = (float*)d_out;

    int N = in_sizes[0] / 256;
    int E = in_sizes[1] / 2;

    cudaFuncSetAttribute(gemm_tc, cudaFuncAttributeMaxDynamicSharedMemorySize,
                         SM_TOTAL);

    // --- CSR build ---
    detect_dtype<<<1, 1>>>(ei, N);
    zero_counts<<<(N + 255) / 256, 256>>>(N);
    hist_kernel<<<(E + 255) / 256, 256>>>(ei, E, N);
    alloc_rows<<<(N + 1023) / 1024, 1024>>>(N);
    scatter_kernel<<<(E + 255) / 256, 256>>>(ei, E, N);

    dim3 grid_l((N + 127) / 128, 4);
    dim3 grid_c((N + 127) / 128, 1);
    int nx2 = N * 128;          // N*256/2
    int nw2 = 256 * 256 / 2;
    int nc2 = 64 * 256 / 2;

    // --- layer 1 ---
    conv_split_x<<<(nx2 + 255) / 256, 256>>>(x, nx2);
    conv_split_w<<<(nw2 + 255) / 256, 256>>>(W1, nw2);
    gemm_tc<<<grid_l, 256, SM_TOTAL>>>(nullptr, nullptr, 0, N, 256, as1, ad1);
    gat_agg<<<N, 128>>>(g1, b1, m1, v1);

    // --- layer 2 ---
    conv_split_w<<<(nw2 + 255) / 256, 256>>>(W2, nw2);
    gemm_tc<<<grid_l, 256, SM_TOTAL>>>(nullptr, nullptr, 0, N, 256, as2, ad2);
    gat_agg<<<N, 128>>>(g2, b2, m2, v2);

    // --- classifier ---
    conv_split_w<<<(nc2 + 255) / 256, 256>>>(Wc, nc2);
    gemm_tc<<<grid_c, 256, SM_TOTAL>>>(bc, out, 1, N, 64, nullptr, nullptr);
}

// round 9
// speedup vs baseline: 1.9949x; 1.0368x over previous
#include <cuda_runtime.h>
#include <cuda_bf16.h>
#include <cstdint>

// ---------------------------------------------------------------------------
// GATModel on GB300: tcgen05 bf16 split-GEMM + chunked two-phase GAT aggregate
// N=50000, E=500000, F=256, H=4, D=64, OUT=64
// R9: gat_agg restructure — per-(edge,head) weight computed ONCE (was 128x).
// ---------------------------------------------------------------------------

#if defined(__CUDA_ARCH_FEAT_SM103_ALL) || defined(__CUDA_ARCH_FEAT_SM100_ALL) || \
    defined(__CUDA_ARCH_FEAT_SM101_ALL) || defined(__CUDA_ARCH_SPECIFIC__)
#define TC_OK 1
#else
#define TC_OK 0
#endif

#define NMAX 50000
#define EMAX 500000

__device__ float          g_buf1[NMAX * 256];   // GEMM output h (fp32)
__device__ __nv_bfloat16  g_a_hi[NMAX * 256];   // GEMM A input, hi part
__device__ __nv_bfloat16  g_a_lo[NMAX * 256];   // GEMM A input, lo part
__device__ __nv_bfloat16  g_wb_hi[256 * 256];   // weight B, hi
__device__ __nv_bfloat16  g_wb_lo[256 * 256];   // weight B, lo
__device__ float g_ssrc[NMAX * 4];
__device__ float g_sdst[NMAX * 4];
__device__ int   g_counts[NMAX];
__device__ int   g_rowbeg[NMAX];
__device__ int   g_rowend[NMAX];
__device__ int   g_cursor[NMAX];
__device__ int   g_csrc[EMAX];
__device__ int   g_is64;
__device__ int   g_total;

// ---------------- edge_index dtype detection ----------------
__global__ void detect_dtype(const void* __restrict__ ei, int N) {
    const long long* p = (const long long*)ei;
    int ok = 1;
    for (int i = 0; i < 16; i++) {
        long long v = p[i];
        if (v < 0 || v >= (long long)N) ok = 0;
    }
    g_is64 = ok;
}
__device__ __forceinline__ int load_idx(const void* ei, long long pos) {
    if (g_is64) return (int)((const long long*)ei)[pos];
    return ((const int*)ei)[pos];
}

// ---------------- CSR build ----------------
__global__ void zero_counts(int N) {
    int i = blockIdx.x * blockDim.x + threadIdx.x;
    if (i < N) g_counts[i] = 0;
    if (i == 0) g_total = 0;
}
__global__ void hist_kernel(const void* __restrict__ ei, int E, int N) {
    int e = blockIdx.x * blockDim.x + threadIdx.x;
    if (e < E) {
        int d = load_idx(ei, (long long)E + e);
        if (d >= 0 && d < N) atomicAdd(&g_counts[d], 1);
    }
}
__global__ void __launch_bounds__(1024)
alloc_rows(int N) {
    __shared__ int sh[1024];
    __shared__ int sbase;
    int tid = threadIdx.x;
    int i = blockIdx.x * 1024 + tid;
    int c = (i < N) ? g_counts[i] : 0;
    sh[tid] = c;
    __syncthreads();
    for (int off = 1; off < 1024; off <<= 1) {
        int v = (tid >= off) ? sh[tid - off] : 0;
        __syncthreads();
        sh[tid] += v;
        __syncthreads();
    }
    if (tid == 1023) sbase = atomicAdd(&g_total, sh[1023]);
    __syncthreads();
    if (i < N) {
        int b = sbase + sh[tid] - c;
        g_rowbeg[i] = b;
        g_rowend[i] = b + c;
        g_cursor[i] = b;
    }
}
__global__ void scatter_kernel(const void* __restrict__ ei, int E, int N) {
    int e = blockIdx.x * blockDim.x + threadIdx.x;
    if (e < E) {
        int d = load_idx(ei, (long long)E + e);
        int s = load_idx(ei, e);
        if (d >= 0 && d < N && s >= 0 && s < N) {
            int pos = atomicAdd(&g_cursor[d], 1);
            if (pos >= 0 && pos < E) g_csrc[pos] = s;
        }
    }
}

// ---------------- fp32 -> bf16 hi/lo split conversions ----------------
__global__ void conv_split_x(const float* __restrict__ src, int n2) {
    int i = blockIdx.x * blockDim.x + threadIdx.x;
    if (i < n2) {
        float2 v = ((const float2*)src)[i];
        __nv_bfloat16 h0 = __float2bfloat16(v.x);
        __nv_bfloat16 h1 = __float2bfloat16(v.y);
        ((__nv_bfloat162*)g_a_hi)[i] = __halves2bfloat162(h0, h1);
        ((__nv_bfloat162*)g_a_lo)[i] = __halves2bfloat162(
            __float2bfloat16(v.x - __bfloat162float(h0)),
            __float2bfloat16(v.y - __bfloat162float(h1)));
    }
}
__global__ void conv_split_w(const float* __restrict__ src, int n2) {
    int i = blockIdx.x * blockDim.x + threadIdx.x;
    if (i < n2) {
        float2 v = ((const float2*)src)[i];
        __nv_bfloat16 h0 = __float2bfloat16(v.x);
        __nv_bfloat16 h1 = __float2bfloat16(v.y);
        ((__nv_bfloat162*)g_wb_hi)[i] = __halves2bfloat162(h0, h1);
        ((__nv_bfloat162*)g_wb_lo)[i] = __halves2bfloat162(
            __float2bfloat16(v.x - __bfloat162float(h0)),
            __float2bfloat16(v.y - __bfloat162float(h1)));
    }
}

// ---------------- tcgen05 helpers (arch-specific pass only) ----------------
#if TC_OK
__device__ __forceinline__ uint32_t elect_one_pred() {
    uint32_t pred;
    asm volatile("{\n\t.reg .pred p;\n\telect.sync _|p, 0xFFFFFFFF;\n\t"
                 "selp.b32 %0, 1, 0, p;\n\t}" : "=r"(pred));
    return pred;
}
__device__ __forceinline__ uint32_t smem_to_u32(const void* p) {
    uint32_t a;
    asm("{ .reg .u64 t; cvta.to.shared.u64 t, %1; cvt.u32.u64 %0, t; }"
        : "=r"(a) : "l"(p));
    return a;
}
#define MBARRIER_INIT(mbar, count) \
    asm volatile("mbarrier.init.shared.b64 [%0], %1;" \
                 :: "r"((uint32_t)(mbar)), "r"((uint32_t)(count)) : "memory")
#define MBARRIER_WAIT_PARITY(mbar, parity) do { \
    uint32_t _m = (uint32_t)(mbar), _p = (uint32_t)(parity), _d; \
    asm volatile("{\n\t.reg .pred p;\n\t" \
        "mbarrier.try_wait.parity.acquire.cta.shared::cta.b64 p, [%1], %2;\n\t" \
        "selp.b32 %0, 1, 0, p;\n\t}" : "=r"(_d) : "r"(_m), "r"(_p) : "memory"); \
    if (!_d) { \
        asm volatile("{\n\t.reg .pred P1;\n\t" \
            "WL_%=:\n\t" \
            "mbarrier.try_wait.parity.acquire.cta.shared::cta.b64 P1, [%0], %1, 0x989680;\n\t" \
            "@P1 bra.uni WD_%=;\n\tbra.uni WL_%=;\n\tWD_%=:\n\t}" \
            :: "r"(_m), "r"(_p) : "memory"); \
    } \
} while (0)
#define TCGEN05_ALLOC(sr, n) \
    asm volatile("tcgen05.alloc.cta_group::1.sync.aligned.shared::cta.b32 [%0], %1;" \
                 :: "r"((uint32_t)(sr)), "r"((uint32_t)(n)) : "memory")
#define TCGEN05_DEALLOC(t, n) \
    asm volatile("tcgen05.dealloc.cta_group::1.sync.aligned.b32 %0, %1;" \
                 :: "r"(t), "r"((uint32_t)(n)))
#define TCGEN05_RELINQ() \
    asm volatile("tcgen05.relinquish_alloc_permit.cta_group::1.sync.aligned;")
#define TCGEN05_COMMIT(mbar) \
    asm volatile("tcgen05.commit.cta_group::1.mbarrier::arrive::one.shared::cluster.b64 [%0];" \
                 :: "r"((uint32_t)(mbar)) : "memory")
#define TCGEN05_FENCE_AFTER() \
    asm volatile("tcgen05.fence::after_thread_sync;" ::: "memory")
#define TCGEN05_WAIT_LD() \
    asm volatile("tcgen05.wait::ld.sync.aligned;" ::: "memory")
#define TCGEN05_LD_32X32B_X32(r, ta) \
    asm volatile("tcgen05.ld.sync.aligned.32x32b.x32.b32 " \
        "{%0, %1, %2, %3, %4, %5, %6, %7, %8, %9, %10, %11, %12, %13, %14, %15, " \
        " %16, %17, %18, %19, %20, %21, %22, %23, %24, %25, %26, %27, %28, %29, %30, %31}, [%32];" \
        : "=r"((r)[0]), "=r"((r)[1]), "=r"((r)[2]), "=r"((r)[3]), \
          "=r"((r)[4]), "=r"((r)[5]), "=r"((r)[6]), "=r"((r)[7]), \
          "=r"((r)[8]), "=r"((r)[9]), "=r"((r)[10]), "=r"((r)[11]), \
          "=r"((r)[12]), "=r"((r)[13]), "=r"((r)[14]), "=r"((r)[15]), \
          "=r"((r)[16]), "=r"((r)[17]), "=r"((r)[18]), "=r"((r)[19]), \
          "=r"((r)[20]), "=r"((r)[21]), "=r"((r)[22]), "=r"((r)[23]), \
          "=r"((r)[24]), "=r"((r)[25]), "=r"((r)[26]), "=r"((r)[27]), \
          "=r"((r)[28]), "=r"((r)[29]), "=r"((r)[30]), "=r"((r)[31]) \
        : "r"(ta))

__device__ __forceinline__ uint64_t make_desc(uint32_t addr) {
    uint64_t base = (uint64_t(2) << 61) | (uint64_t(1) << 46) |
                    (uint64_t(64) << 32) | (uint64_t(1) << 16);
    return base | ((uint64_t)(addr >> 4) & 0x3FFF);
}
__device__ __forceinline__ void mma_f16_ss(uint32_t d, uint64_t ad, uint64_t bd,
                                           uint32_t idesc, bool en) {
    uint32_t e = en ? 1u : 0u;
    asm volatile("{\n\t.reg .pred p;\n\tsetp.ne.u32 p, %5, 0;\n\t"
                 "tcgen05.mma.cta_group::1.kind::f16 [%0], %1, %2, %3, {%4, %4, %4, %4}, p;\n\t}"
                 :: "r"(d), "l"(ad), "l"(bd), "r"(idesc), "r"(0u), "r"(e)
                 : "memory");
}
#define MMA_IDESC 0x8100490u
#endif  // TC_OK

// ---------------- tcgen05 split-GEMM ----------------
#define SM_TMEM 0
#define SM_MBAR 8
#define SM_A_HI 1024
#define SM_A_LO (1024 + 65536)
#define SM_B_HI (1024 + 131072)
#define SM_B_LO (1024 + 163840)
#define SM_TOTAL (1024 + 196608)

__global__ void __launch_bounds__(256)
gemm_tc(const float* __restrict__ bias,
        float* __restrict__ Cext, int toExt, int M, int Nout,
        const float* __restrict__ a_src, const float* __restrict__ a_dst) {
#if TC_OK
    extern __shared__ char smem[];
    uint32_t sb = smem_to_u32(smem);
    int tid = threadIdx.x;
    int wid = tid >> 5;
    int lane = tid & 31;
    int row0 = blockIdx.x * 128;
    int col0 = blockIdx.y * 64;
    float* C = toExt ? Cext : (float*)g_buf1;

    if (wid == 0) {
        TCGEN05_ALLOC(sb + SM_TMEM, 128);
        TCGEN05_RELINQ();
    }
    if (tid == 0) MBARRIER_INIT(sb + SM_MBAR, 1);
    __syncthreads();
    uint32_t tmem;
    asm volatile("ld.shared.b32 %0, [%1];" : "=r"(tmem) : "r"(sb + SM_TMEM));

    // ---- load A tiles (hi: threads 0-127; lo: threads 128-255) ----
    {
        int r = tid & 127;
        const __nv_bfloat16* srcA = (tid < 128) ? g_a_hi : g_a_lo;
        int base = (tid < 128) ? SM_A_HI : SM_A_LO;
        int grow = row0 + r;
        const uint4* src = (const uint4*)(srcA + (size_t)grow * 256);
        int arow = r >> 3, irow = r & 7;
#pragma unroll
        for (int c = 0; c < 32; c++) {
            uint4 v = (grow < M) ? src[c] : make_uint4(0u, 0u, 0u, 0u);
            int off = (arow + (c >> 3) * 16) * 1024 + irow * 128 + (c & 7) * 16;
            off ^= (off >> 3) & 0x70;
            *(uint4*)(smem + base + off) = v;
        }
    }
    // ---- load B tiles ----
    {
        int rb = tid >> 1;
        int r = rb & 63;
        const __nv_bfloat16* srcB = (rb < 64) ? g_wb_hi : g_wb_lo;
        int base = (rb < 64) ? SM_B_HI : SM_B_LO;
        const uint4* src = (const uint4*)(srcB + (size_t)(col0 + r) * 256);
        int arow = r >> 3, irow = r & 7;
        int cs = (tid & 1) * 16;
#pragma unroll
        for (int q = 0; q < 16; q++) {
            int c = cs + q;
            uint4 v = src[c];
            int off = (arow + (c >> 3) * 8) * 1024 + irow * 128 + (c & 7) * 16;
            off ^= (off >> 3) & 0x70;
            *(uint4*)(smem + base + off) = v;
        }
    }
    __syncthreads();
    asm volatile("fence.proxy.async.shared::cta;" ::: "memory");

    // ---- issue 3x16 MMAs (hh, hl, lh) ----
    if (wid == 0) {
        if (elect_one_pred()) {
            uint64_t dA_hi = make_desc(sb + SM_A_HI);
            uint64_t dA_lo = make_desc(sb + SM_A_LO);
            uint64_t dB_hi = make_desc(sb + SM_B_HI);
            uint64_t dB_lo = make_desc(sb + SM_B_LO);
#pragma unroll
            for (int term = 0; term < 3; term++) {
                uint64_t da = (term == 2) ? dA_lo : dA_hi;
                uint64_t db = (term == 1) ? dB_lo : dB_hi;
#pragma unroll
                for (int kc = 0; kc < 16; kc++) {
                    uint64_t offA = (uint64_t)((kc >> 2) * 1024 + (kc & 3) * 2);
                    uint64_t offB = (uint64_t)((kc >> 2) * 512 + (kc & 3) * 2);
                    mma_f16_ss(tmem, da + offA, db + offB, MMA_IDESC,
                               !(term == 0 && kc == 0));
                }
            }
            TCGEN05_COMMIT(sb + SM_MBAR);
        }
    }

    MBARRIER_WAIT_PARITY(sb + SM_MBAR, 0);
    TCGEN05_FENCE_AFTER();

    // ---- epilogue ----
    if (wid < 4) {
        uint32_t d0[32], d1[32];
        TCGEN05_LD_32X32B_X32(d0, tmem);
        TCGEN05_LD_32X32B_X32(d1, tmem + 32);
        TCGEN05_WAIT_LD();
        int r = row0 + wid * 32 + lane;
        if (r < M) {
            float cv[64];
#pragma unroll
            for (int j = 0; j < 32; j++) {
                cv[j] = __uint_as_float(d0[j]);
                cv[32 + j] = __uint_as_float(d1[j]);
            }
            if (bias) {
#pragma unroll
                for (int j = 0; j < 64; j++) cv[j] += bias[col0 + j];
            }
            float* crow = C + (size_t)r * Nout + col0;
#pragma unroll
            for (int q = 0; q < 16; q++) {
                *(float4*)(crow + q * 4) =
                    make_float4(cv[4 * q], cv[4 * q + 1], cv[4 * q + 2], cv[4 * q + 3]);
            }
            if (a_src) {
                float vs = 0.f, vd = 0.f;
#pragma unroll
                for (int j = 0; j < 64; j++) {
                    vs = fmaf(cv[j], a_src[col0 + j], vs);
                    vd = fmaf(cv[j], a_dst[col0 + j], vd);
                }
                g_ssrc[r * 4 + blockIdx.y] = vs;
                g_sdst[r * 4 + blockIdx.y] = vd;
            }
        }
    }
    __syncthreads();
    if (tid == 0)
        asm volatile("mbarrier.inval.shared.b64 [%0];" :: "r"(sb + SM_MBAR) : "memory");
    if (wid == 0) TCGEN05_DEALLOC(tmem, 128);
#endif  // TC_OK
}

// ---------------- GAT aggregate + BN + ELU (chunked two-phase) ----------------
// Per node block (128 threads). Chunks of 32 edges:
//   Phase A: thread (e4 = tid>>2, h = tid&3) computes weight for (edge, head)
//            exactly once -> smem wgt[32][4]; sidx[32] caches src indices.
//   Phase B: thread owns channels c=2*tid (head = tid>>5); accumulates over
//            the chunk reading wgt via smem broadcast, hfeat coalesced.
__global__ void __launch_bounds__(128)
gat_agg(const float* __restrict__ gamma, const float* __restrict__ beta,
        const float* __restrict__ mean, const float* __restrict__ var) {
    __shared__ float wgt[32][4];
    __shared__ int   sidx[32];
    __shared__ float smax[4];

    int n = blockIdx.x;
    int tid = threadIdx.x;
    int head = tid >> 5;
    int lane = tid & 31;
    int beg = g_rowbeg[n];
    int end = g_rowend[n];
    const float* hfeat = g_buf1;

    // ---- per-head max (warp w handles head w; implicit 0 included) ----
    {
        float sd_h = g_sdst[n * 4 + head];
        float m = 0.f;
        for (int i = beg + lane; i < end; i += 32) {
            int s = g_csrc[i];
            float e = g_ssrc[s * 4 + head] + sd_h;
            e = (e >= 0.f) ? e : 0.2f * e;
            m = fmaxf(m, e);
        }
#pragma unroll
        for (int o = 16; o; o >>= 1) m = fmaxf(m, __shfl_xor_sync(~0u, m, o));
        if (lane == 0) smax[head] = m;
    }
    __syncthreads();

    // weight-compute mapping for phase A
    int eh = tid & 3;              // head for weight compute
    int eo = tid >> 2;             // edge offset within chunk (0..31)
    float sd_eh = g_sdst[n * 4 + eh];
    float m_eh = smax[eh];

    float acc0 = 0.f, acc1 = 0.f, ws = 0.f;
    int c = tid * 2;

    for (int base = beg; base < end; base += 32) {
        int cnt = min(32, end - base);
        // Phase A: one weight per (edge, head)
        {
            float w = 0.f;
            int s = -1;
            if (eo < cnt) {
                s = g_csrc[base + eo];
                float e = g_ssrc[s * 4 + eh] + sd_eh;
                e = (e >= 0.f) ? e : 0.2f * e;
                w = __expf(e - m_eh);
            }
            wgt[eo][eh] = w;
            if (eh == 0) sidx[eo] = s;
        }
        __syncthreads();
        // Phase B: accumulate channels
        for (int j = 0; j < cnt; j++) {
            float w = wgt[j][head];
            ws += w;
            float2 hv = *(const float2*)&hfeat[(size_t)sidx[j] * 256 + c];
            acc0 = fmaf(w, hv.x, acc0);
            acc1 = fmaf(w, hv.y, acc1);
        }
        __syncthreads();
    }

    float inv = 1.f / fmaxf(ws, 1e-9f);
    float o0 = acc0 * inv;
    float o1 = acc1 * inv;

    o0 = (o0 - mean[c]) * rsqrtf(var[c] + 1e-5f) * gamma[c] + beta[c];
    o1 = (o1 - mean[c + 1]) * rsqrtf(var[c + 1] + 1e-5f) * gamma[c + 1] + beta[c + 1];
    o0 = (o0 > 0.f) ? o0 : expm1f(o0);
    o1 = (o1 > 0.f) ? o1 : expm1f(o1);

    __nv_bfloat16 h0 = __float2bfloat16(o0);
    __nv_bfloat16 h1 = __float2bfloat16(o1);
    size_t idx2 = ((size_t)n * 256 + c) >> 1;
    ((__nv_bfloat162*)g_a_hi)[idx2] = __halves2bfloat162(h0, h1);
    ((__nv_bfloat162*)g_a_lo)[idx2] = __halves2bfloat162(
        __float2bfloat16(o0 - __bfloat162float(h0)),
        __float2bfloat16(o1 - __bfloat162float(h1)));
}

// ---------------------------------------------------------------------------
extern "C" void kernel_launch(void* const* d_in, const int* in_sizes, int n_in,
                              void* d_out, int out_size) {
    const float* x   = (const float*)d_in[0];
    const void*  ei  = d_in[1];
    const float* W1  = (const float*)d_in[2];
    const float* as1 = (const float*)d_in[3];
    const float* ad1 = (const float*)d_in[4];
    const float* g1  = (const float*)d_in[5];
    const float* b1  = (const float*)d_in[6];
    const float* m1  = (const float*)d_in[7];
    const float* v1  = (const float*)d_in[8];
    const float* W2  = (const float*)d_in[9];
    const float* as2 = (const float*)d_in[10];
    const float* ad2 = (const float*)d_in[11];
    const float* g2  = (const float*)d_in[12];
    const float* b2  = (const float*)d_in[13];
    const float* m2  = (const float*)d_in[14];
    const float* v2  = (const float*)d_in[15];
    const float* Wc  = (const float*)d_in[16];
    const float* bc  = (const float*)d_in[17];
    float* out = (float*)d_out;

    int N = in_sizes[0] / 256;
    int E = in_sizes[1] / 2;

    cudaFuncSetAttribute(gemm_tc, cudaFuncAttributeMaxDynamicSharedMemorySize,
                         SM_TOTAL);

    // --- CSR build ---
    detect_dtype<<<1, 1>>>(ei, N);
    zero_counts<<<(N + 255) / 256, 256>>>(N);
    hist_kernel<<<(E + 255) / 256, 256>>>(ei, E, N);
    alloc_rows<<<(N + 1023) / 1024, 1024>>>(N);
    scatter_kernel<<<(E + 255) / 256, 256>>>(ei, E, N);

    dim3 grid_l((N + 127) / 128, 4);
    dim3 grid_c((N + 127) / 128, 1);
    int nx2 = N * 128;
    int nw2 = 256 * 256 / 2;
    int nc2 = 64 * 256 / 2;

    // --- layer 1 ---
    conv_split_x<<<(nx2 + 255) / 256, 256>>>(x, nx2);
    conv_split_w<<<(nw2 + 255) / 256, 256>>>(W1, nw2);
    gemm_tc<<<grid_l, 256, SM_TOTAL>>>(nullptr, nullptr, 0, N, 256, as1, ad1);
    gat_agg<<<N, 128>>>(g1, b1, m1, v1);

    // --- layer 2 ---
    conv_split_w<<<(nw2 + 255) / 256, 256>>>(W2, nw2);
    gemm_tc<<<grid_l, 256, SM_TOTAL>>>(nullptr, nullptr, 0, N, 256, as2, ad2);
    gat_agg<<<N, 128>>>(g2, b2, m2, v2);

    // --- classifier ---
    conv_split_w<<<(nc2 + 255) / 256, 256>>>(Wc, nc2);
    gemm_tc<<<grid_c, 256, SM_TOTAL>>>(bc, out, 1, N, 64, nullptr, nullptr);
}

// round 10
// speedup vs baseline: 2.2797x; 1.1428x over previous
#include <cuda_runtime.h>
#include <cuda_bf16.h>
#include <cstdint>

// ---------------------------------------------------------------------------
// GATModel on GB300: tcgen05 bf16 split-GEMM (2-pass K, occ=2, cp.async)
// + chunked two-phase GAT aggregate. N=50000, E=500000, F=256, H=4, D=64.
// R10: GEMM smem 193KB -> 97KB (occ 1 -> 2), cp.async staging, K ping-pong.
// ---------------------------------------------------------------------------

#if defined(__CUDA_ARCH_FEAT_SM103_ALL) || defined(__CUDA_ARCH_FEAT_SM100_ALL) || \
    defined(__CUDA_ARCH_FEAT_SM101_ALL) || defined(__CUDA_ARCH_SPECIFIC__)
#define TC_OK 1
#else
#define TC_OK 0
#endif

#define NMAX 50000
#define EMAX 500000

__device__ float          g_buf1[NMAX * 256];   // GEMM output h (fp32)
__device__ __nv_bfloat16  g_a_hi[NMAX * 256];   // GEMM A input, hi part
__device__ __nv_bfloat16  g_a_lo[NMAX * 256];   // GEMM A input, lo part
__device__ __nv_bfloat16  g_wb_hi[256 * 256];   // weight B, hi
__device__ __nv_bfloat16  g_wb_lo[256 * 256];   // weight B, lo
__device__ float g_ssrc[NMAX * 4];
__device__ float g_sdst[NMAX * 4];
__device__ int   g_counts[NMAX];
__device__ int   g_rowbeg[NMAX];
__device__ int   g_rowend[NMAX];
__device__ int   g_cursor[NMAX];
__device__ int   g_csrc[EMAX];
__device__ int   g_is64;
__device__ int   g_total;

// ---------------- edge_index dtype detection ----------------
__global__ void detect_dtype(const void* __restrict__ ei, int N) {
    const long long* p = (const long long*)ei;
    int ok = 1;
    for (int i = 0; i < 16; i++) {
        long long v = p[i];
        if (v < 0 || v >= (long long)N) ok = 0;
    }
    g_is64 = ok;
}
__device__ __forceinline__ int load_idx(const void* ei, long long pos) {
    if (g_is64) return (int)((const long long*)ei)[pos];
    return ((const int*)ei)[pos];
}

// ---------------- CSR build ----------------
__global__ void zero_counts(int N) {
    int i = blockIdx.x * blockDim.x + threadIdx.x;
    if (i < N) g_counts[i] = 0;
    if (i == 0) g_total = 0;
}
__global__ void hist_kernel(const void* __restrict__ ei, int E, int N) {
    int e = blockIdx.x * blockDim.x + threadIdx.x;
    if (e < E) {
        int d = load_idx(ei, (long long)E + e);
        if (d >= 0 && d < N) atomicAdd(&g_counts[d], 1);
    }
}
__global__ void __launch_bounds__(1024)
alloc_rows(int N) {
    __shared__ int sh[1024];
    __shared__ int sbase;
    int tid = threadIdx.x;
    int i = blockIdx.x * 1024 + tid;
    int c = (i < N) ? g_counts[i] : 0;
    sh[tid] = c;
    __syncthreads();
    for (int off = 1; off < 1024; off <<= 1) {
        int v = (tid >= off) ? sh[tid - off] : 0;
        __syncthreads();
        sh[tid] += v;
        __syncthreads();
    }
    if (tid == 1023) sbase = atomicAdd(&g_total, sh[1023]);
    __syncthreads();
    if (i < N) {
        int b = sbase + sh[tid] - c;
        g_rowbeg[i] = b;
        g_rowend[i] = b + c;
        g_cursor[i] = b;
    }
}
__global__ void scatter_kernel(const void* __restrict__ ei, int E, int N) {
    int e = blockIdx.x * blockDim.x + threadIdx.x;
    if (e < E) {
        int d = load_idx(ei, (long long)E + e);
        int s = load_idx(ei, e);
        if (d >= 0 && d < N && s >= 0 && s < N) {
            int pos = atomicAdd(&g_cursor[d], 1);
            if (pos >= 0 && pos < E) g_csrc[pos] = s;
        }
    }
}

// ---------------- fp32 -> bf16 hi/lo split conversions ----------------
__global__ void conv_split_x(const float* __restrict__ src, int n2) {
    int i = blockIdx.x * blockDim.x + threadIdx.x;
    if (i < n2) {
        float2 v = ((const float2*)src)[i];
        __nv_bfloat16 h0 = __float2bfloat16(v.x);
        __nv_bfloat16 h1 = __float2bfloat16(v.y);
        ((__nv_bfloat162*)g_a_hi)[i] = __halves2bfloat162(h0, h1);
        ((__nv_bfloat162*)g_a_lo)[i] = __halves2bfloat162(
            __float2bfloat16(v.x - __bfloat162float(h0)),
            __float2bfloat16(v.y - __bfloat162float(h1)));
    }
}
__global__ void conv_split_w(const float* __restrict__ src, int n2) {
    int i = blockIdx.x * blockDim.x + threadIdx.x;
    if (i < n2) {
        float2 v = ((const float2*)src)[i];
        __nv_bfloat16 h0 = __float2bfloat16(v.x);
        __nv_bfloat16 h1 = __float2bfloat16(v.y);
        ((__nv_bfloat162*)g_wb_hi)[i] = __halves2bfloat162(h0, h1);
        ((__nv_bfloat162*)g_wb_lo)[i] = __halves2bfloat162(
            __float2bfloat16(v.x - __bfloat162float(h0)),
            __float2bfloat16(v.y - __bfloat162float(h1)));
    }
}

// ---------------- tcgen05 helpers (arch-specific pass only) ----------------
#if TC_OK
__device__ __forceinline__ uint32_t elect_one_pred() {
    uint32_t pred;
    asm volatile("{\n\t.reg .pred p;\n\telect.sync _|p, 0xFFFFFFFF;\n\t"
                 "selp.b32 %0, 1, 0, p;\n\t}" : "=r"(pred));
    return pred;
}
__device__ __forceinline__ uint32_t smem_to_u32(const void* p) {
    uint32_t a;
    asm("{ .reg .u64 t; cvta.to.shared.u64 t, %1; cvt.u32.u64 %0, t; }"
        : "=r"(a) : "l"(p));
    return a;
}
#define MBARRIER_INIT(mbar, count) \
    asm volatile("mbarrier.init.shared.b64 [%0], %1;" \
                 :: "r"((uint32_t)(mbar)), "r"((uint32_t)(count)) : "memory")
#define MBARRIER_WAIT_PARITY(mbar, parity) do { \
    uint32_t _m = (uint32_t)(mbar), _p = (uint32_t)(parity), _d; \
    asm volatile("{\n\t.reg .pred p;\n\t" \
        "mbarrier.try_wait.parity.acquire.cta.shared::cta.b64 p, [%1], %2;\n\t" \
        "selp.b32 %0, 1, 0, p;\n\t}" : "=r"(_d) : "r"(_m), "r"(_p) : "memory"); \
    if (!_d) { \
        asm volatile("{\n\t.reg .pred P1;\n\t" \
            "WL_%=:\n\t" \
            "mbarrier.try_wait.parity.acquire.cta.shared::cta.b64 P1, [%0], %1, 0x989680;\n\t" \
            "@P1 bra.uni WD_%=;\n\tbra.uni WL_%=;\n\tWD_%=:\n\t}" \
            :: "r"(_m), "r"(_p) : "memory"); \
    } \
} while (0)
#define TCGEN05_ALLOC(sr, n) \
    asm volatile("tcgen05.alloc.cta_group::1.sync.aligned.shared::cta.b32 [%0], %1;" \
                 :: "r"((uint32_t)(sr)), "r"((uint32_t)(n)) : "memory")
#define TCGEN05_DEALLOC(t, n) \
    asm volatile("tcgen05.dealloc.cta_group::1.sync.aligned.b32 %0, %1;" \
                 :: "r"(t), "r"((uint32_t)(n)))
#define TCGEN05_RELINQ() \
    asm volatile("tcgen05.relinquish_alloc_permit.cta_group::1.sync.aligned;")
#define TCGEN05_COMMIT(mbar) \
    asm volatile("tcgen05.commit.cta_group::1.mbarrier::arrive::one.shared::cluster.b64 [%0];" \
                 :: "r"((uint32_t)(mbar)) : "memory")
#define TCGEN05_FENCE_AFTER() \
    asm volatile("tcgen05.fence::after_thread_sync;" ::: "memory")
#define TCGEN05_WAIT_LD() \
    asm volatile("tcgen05.wait::ld.sync.aligned;" ::: "memory")
#define TCGEN05_LD_32X32B_X32(r, ta) \
    asm volatile("tcgen05.ld.sync.aligned.32x32b.x32.b32 " \
        "{%0, %1, %2, %3, %4, %5, %6, %7, %8, %9, %10, %11, %12, %13, %14, %15, " \
        " %16, %17, %18, %19, %20, %21, %22, %23, %24, %25, %26, %27, %28, %29, %30, %31}, [%32];" \
        : "=r"((r)[0]), "=r"((r)[1]), "=r"((r)[2]), "=r"((r)[3]), \
          "=r"((r)[4]), "=r"((r)[5]), "=r"((r)[6]), "=r"((r)[7]), \
          "=r"((r)[8]), "=r"((r)[9]), "=r"((r)[10]), "=r"((r)[11]), \
          "=r"((r)[12]), "=r"((r)[13]), "=r"((r)[14]), "=r"((r)[15]), \
          "=r"((r)[16]), "=r"((r)[17]), "=r"((r)[18]), "=r"((r)[19]), \
          "=r"((r)[20]), "=r"((r)[21]), "=r"((r)[22]), "=r"((r)[23]), \
          "=r"((r)[24]), "=r"((r)[25]), "=r"((r)[26]), "=r"((r)[27]), \
          "=r"((r)[28]), "=r"((r)[29]), "=r"((r)[30]), "=r"((r)[31]) \
        : "r"(ta))
#define CP_ASYNC16(dst, src) \
    asm volatile("cp.async.cg.shared.global [%0], [%1], 16;" \
                 :: "r"((uint32_t)(dst)), "l"(src) : "memory")
#define CP_WAIT_ALL() \
    asm volatile("cp.async.wait_all;" ::: "memory")

__device__ __forceinline__ uint64_t make_desc(uint32_t addr) {
    uint64_t base = (uint64_t(2) << 61) | (uint64_t(1) << 46) |
                    (uint64_t(64) << 32) | (uint64_t(1) << 16);
    return base | ((uint64_t)(addr >> 4) & 0x3FFF);
}
__device__ __forceinline__ void mma_f16_ss(uint32_t d, uint64_t ad, uint64_t bd,
                                           uint32_t idesc, bool en) {
    uint32_t e = en ? 1u : 0u;
    asm volatile("{\n\t.reg .pred p;\n\tsetp.ne.u32 p, %5, 0;\n\t"
                 "tcgen05.mma.cta_group::1.kind::f16 [%0], %1, %2, %3, {%4, %4, %4, %4}, p;\n\t}"
                 :: "r"(d), "l"(ad), "l"(bd), "r"(idesc), "r"(0u), "r"(e)
                 : "memory");
}
#define MMA_IDESC 0x8100490u
#endif  // TC_OK

// ---------------- tcgen05 split-GEMM, 2-pass K, occ=2 ----------------
// Per CTA: C[128,64] = A[128,256]*B[64,256]^T, hi/lo bf16 split (3 terms),
// K processed in 2 halves of 128 reusing the same smem buffers.
// smem: A_hi 32K + A_lo 32K + B_hi 16K + B_lo 16K + 1K hdr = 97.5KB -> occ 2.
#define SM_TMEM 0
#define SM_MBAR 8
#define SM_A_HI 1024
#define SM_A_LO (SM_A_HI + 32768)
#define SM_B_HI (SM_A_LO + 32768)
#define SM_B_LO (SM_B_HI + 16384)
#define SM_TOTAL (SM_B_LO + 16384)

__global__ void __launch_bounds__(256)
gemm_tc(const float* __restrict__ bias,
        float* __restrict__ Cext, int toExt, int M, int Nout,
        const float* __restrict__ a_src, const float* __restrict__ a_dst) {
#if TC_OK
    extern __shared__ char smem[];
    uint32_t sb = smem_to_u32(smem);
    int tid = threadIdx.x;
    int wid = tid >> 5;
    int lane = tid & 31;
    int row0 = blockIdx.x * 128;
    int col0 = blockIdx.y * 64;
    float* C = toExt ? Cext : (float*)g_buf1;

    if (wid == 0) {
        TCGEN05_ALLOC(sb + SM_TMEM, 128);
        TCGEN05_RELINQ();
    }
    if (tid == 0) MBARRIER_INIT(sb + SM_MBAR, 1);
    __syncthreads();
    uint32_t tmem;
    asm volatile("ld.shared.b32 %0, [%1];" : "=r"(tmem) : "r"(sb + SM_TMEM));

    // per-thread load mappings (constant across passes)
    int ar = tid & 127;                          // A row
    int a_base = (tid < 128) ? SM_A_HI : SM_A_LO;
    const __nv_bfloat16* a_srcp =
        ((tid < 128) ? g_a_hi : g_a_lo) + (size_t)(row0 + ar) * 256;
    int a_arow = ar >> 3, a_irow = ar & 7;
    bool a_ok = (row0 + ar) < M;

    int rb = tid >> 1;                           // B rowbuf 0..127
    int br = rb & 63;
    int b_base = (rb < 64) ? SM_B_HI : SM_B_LO;
    const __nv_bfloat16* b_srcp =
        ((rb < 64) ? g_wb_hi : g_wb_lo) + (size_t)(col0 + br) * 256;
    int b_arow = br >> 3, b_irow = br & 7;
    int b_cs = (tid & 1) * 8;                    // uint4 offset within half-K row

#pragma unroll
    for (int pass = 0; pass < 2; pass++) {
        if (pass == 1) {
            // MMA of pass 0 must finish before smem is overwritten
            MBARRIER_WAIT_PARITY(sb + SM_MBAR, 0);
        }
        // ---- stage A half (128 rows x 128 bf16 = 16 uint4/row) ----
        {
            const uint4* src = (const uint4*)(a_srcp + pass * 128);
#pragma unroll
            for (int c = 0; c < 16; c++) {
                int off = (a_arow + (c >> 3) * 16) * 1024 + a_irow * 128 + (c & 7) * 16;
                off ^= (off >> 3) & 0x70;
                if (a_ok) CP_ASYNC16(sb + a_base + off, src + c);
                else *(uint4*)(smem + a_base + off) = make_uint4(0u, 0u, 0u, 0u);
            }
        }
        // ---- stage B half (64 rows x 128 bf16; 2 threads/rowbuf) ----
        {
            const uint4* src = (const uint4*)(b_srcp + pass * 128);
#pragma unroll
            for (int q = 0; q < 8; q++) {
                int c = b_cs + q;
                int off = (b_arow + (c >> 3) * 8) * 1024 + b_irow * 128 + (c & 7) * 16;
                off ^= (off >> 3) & 0x70;
                CP_ASYNC16(sb + b_base + off, src + c);
            }
        }
        CP_WAIT_ALL();
        __syncthreads();
        asm volatile("fence.proxy.async.shared::cta;" ::: "memory");

        // ---- issue 3 terms x 8 k-chunks ----
        if (wid == 0) {
            if (elect_one_pred()) {
                uint64_t dA_hi = make_desc(sb + SM_A_HI);
                uint64_t dA_lo = make_desc(sb + SM_A_LO);
                uint64_t dB_hi = make_desc(sb + SM_B_HI);
                uint64_t dB_lo = make_desc(sb + SM_B_LO);
#pragma unroll
                for (int term = 0; term < 3; term++) {
                    uint64_t da = (term == 2) ? dA_lo : dA_hi;
                    uint64_t db = (term == 1) ? dB_lo : dB_hi;
#pragma unroll
                    for (int kc = 0; kc < 8; kc++) {
                        uint64_t offA = (uint64_t)((kc >> 2) * 1024 + (kc & 3) * 2);
                        uint64_t offB = (uint64_t)((kc >> 2) * 512 + (kc & 3) * 2);
                        mma_f16_ss(tmem, da + offA, db + offB, MMA_IDESC,
                                   !(pass == 0 && term == 0 && kc == 0));
                    }
                }
                TCGEN05_COMMIT(sb + SM_MBAR);
            }
        }
        __syncthreads();
    }

    MBARRIER_WAIT_PARITY(sb + SM_MBAR, 1);
    TCGEN05_FENCE_AFTER();

    // ---- epilogue: warps 0-3 read D rows, fp32 C (+bias) + fused scores ----
    if (wid < 4) {
        uint32_t d0[32], d1[32];
        TCGEN05_LD_32X32B_X32(d0, tmem);
        TCGEN05_LD_32X32B_X32(d1, tmem + 32);
        TCGEN05_WAIT_LD();
        int r = row0 + wid * 32 + lane;
        if (r < M) {
            float cv[64];
#pragma unroll
            for (int j = 0; j < 32; j++) {
                cv[j] = __uint_as_float(d0[j]);
                cv[32 + j] = __uint_as_float(d1[j]);
            }
            if (bias) {
#pragma unroll
                for (int j = 0; j < 64; j++) cv[j] += bias[col0 + j];
            }
            float* crow = C + (size_t)r * Nout + col0;
#pragma unroll
            for (int q = 0; q < 16; q++) {
                *(float4*)(crow + q * 4) =
                    make_float4(cv[4 * q], cv[4 * q + 1], cv[4 * q + 2], cv[4 * q + 3]);
            }
            if (a_src) {
                float vs = 0.f, vd = 0.f;
#pragma unroll
                for (int j = 0; j < 64; j++) {
                    vs = fmaf(cv[j], a_src[col0 + j], vs);
                    vd = fmaf(cv[j], a_dst[col0 + j], vd);
                }
                g_ssrc[r * 4 + blockIdx.y] = vs;
                g_sdst[r * 4 + blockIdx.y] = vd;
            }
        }
    }
    __syncthreads();
    if (tid == 0)
        asm volatile("mbarrier.inval.shared.b64 [%0];" :: "r"(sb + SM_MBAR) : "memory");
    if (wid == 0) TCGEN05_DEALLOC(tmem, 128);
#endif  // TC_OK
}

// ---------------- GAT aggregate + BN + ELU (chunked two-phase) ----------------
__global__ void __launch_bounds__(128)
gat_agg(const float* __restrict__ gamma, const float* __restrict__ beta,
        const float* __restrict__ mean, const float* __restrict__ var) {
    __shared__ float wgt[32][4];
    __shared__ int   sidx[32];
    __shared__ float smax[4];

    int n = blockIdx.x;
    int tid = threadIdx.x;
    int head = tid >> 5;
    int lane = tid & 31;
    int beg = g_rowbeg[n];
    int end = g_rowend[n];
    const float* hfeat = g_buf1;

    {
        float sd_h = g_sdst[n * 4 + head];
        float m = 0.f;
        for (int i = beg + lane; i < end; i += 32) {
            int s = g_csrc[i];
            float e = g_ssrc[s * 4 + head] + sd_h;
            e = (e >= 0.f) ? e : 0.2f * e;
            m = fmaxf(m, e);
        }
#pragma unroll
        for (int o = 16; o; o >>= 1) m = fmaxf(m, __shfl_xor_sync(~0u, m, o));
        if (lane == 0) smax[head] = m;
    }
    __syncthreads();

    int eh = tid & 3;
    int eo = tid >> 2;
    float sd_eh = g_sdst[n * 4 + eh];
    float m_eh = smax[eh];

    float acc0 = 0.f, acc1 = 0.f, ws = 0.f;
    int c = tid * 2;

    for (int base = beg; base < end; base += 32) {
        int cnt = min(32, end - base);
        {
            float w = 0.f;
            int s = -1;
            if (eo < cnt) {
                s = g_csrc[base + eo];
                float e = g_ssrc[s * 4 + eh] + sd_eh;
                e = (e >= 0.f) ? e : 0.2f * e;
                w = __expf(e - m_eh);
            }
            wgt[eo][eh] = w;
            if (eh == 0) sidx[eo] = s;
        }
        __syncthreads();
        for (int j = 0; j < cnt; j++) {
            float w = wgt[j][head];
            ws += w;
            float2 hv = *(const float2*)&hfeat[(size_t)sidx[j] * 256 + c];
            acc0 = fmaf(w, hv.x, acc0);
            acc1 = fmaf(w, hv.y, acc1);
        }
        __syncthreads();
    }

    float inv = 1.f / fmaxf(ws, 1e-9f);
    float o0 = acc0 * inv;
    float o1 = acc1 * inv;

    o0 = (o0 - mean[c]) * rsqrtf(var[c] + 1e-5f) * gamma[c] + beta[c];
    o1 = (o1 - mean[c + 1]) * rsqrtf(var[c + 1] + 1e-5f) * gamma[c + 1] + beta[c + 1];
    o0 = (o0 > 0.f) ? o0 : expm1f(o0);
    o1 = (o1 > 0.f) ? o1 : expm1f(o1);

    __nv_bfloat16 h0 = __float2bfloat16(o0);
    __nv_bfloat16 h1 = __float2bfloat16(o1);
    size_t idx2 = ((size_t)n * 256 + c) >> 1;
    ((__nv_bfloat162*)g_a_hi)[idx2] = __halves2bfloat162(h0, h1);
    ((__nv_bfloat162*)g_a_lo)[idx2] = __halves2bfloat162(
        __float2bfloat16(o0 - __bfloat162float(h0)),
        __float2bfloat16(o1 - __bfloat162float(h1)));
}

// ---------------------------------------------------------------------------
extern "C" void kernel_launch(void* const* d_in, const int* in_sizes, int n_in,
                              void* d_out, int out_size) {
    const float* x   = (const float*)d_in[0];
    const void*  ei  = d_in[1];
    const float* W1  = (const float*)d_in[2];
    const float* as1 = (const float*)d_in[3];
    const float* ad1 = (const float*)d_in[4];
    const float* g1  = (const float*)d_in[5];
    const float* b1  = (const float*)d_in[6];
    const float* m1  = (const float*)d_in[7];
    const float* v1  = (const float*)d_in[8];
    const float* W2  = (const float*)d_in[9];
    const float* as2 = (const float*)d_in[10];
    const float* ad2 = (const float*)d_in[11];
    const float* g2  = (const float*)d_in[12];
    const float* b2  = (const float*)d_in[13];
    const float* m2  = (const float*)d_in[14];
    const float* v2  = (const float*)d_in[15];
    const float* Wc  = (const float*)d_in[16];
    const float* bc  = (const float*)d_in[17];
    float* out = (float*)d_out;

    int N = in_sizes[0] / 256;
    int E = in_sizes[1] / 2;

    cudaFuncSetAttribute(gemm_tc, cudaFuncAttributeMaxDynamicSharedMemorySize,
                         SM_TOTAL);

    // --- CSR build ---
    detect_dtype<<<1, 1>>>(ei, N);
    zero_counts<<<(N + 255) / 256, 256>>>(N);
    hist_kernel<<<(E + 255) / 256, 256>>>(ei, E, N);
    alloc_rows<<<(N + 1023) / 1024, 1024>>>(N);
    scatter_kernel<<<(E + 255) / 256, 256>>>(ei, E, N);

    dim3 grid_l((N + 127) / 128, 4);
    dim3 grid_c((N + 127) / 128, 1);
    int nx2 = N * 128;
    int nw2 = 256 * 256 / 2;
    int nc2 = 64 * 256 / 2;

    // --- layer 1 ---
    conv_split_x<<<(nx2 + 255) / 256, 256>>>(x, nx2);
    conv_split_w<<<(nw2 + 255) / 256, 256>>>(W1, nw2);
    gemm_tc<<<grid_l, 256, SM_TOTAL>>>(nullptr, nullptr, 0, N, 256, as1, ad1);
    gat_agg<<<N, 128>>>(g1, b1, m1, v1);

    // --- layer 2 ---
    conv_split_w<<<(nw2 + 255) / 256, 256>>>(W2, nw2);
    gemm_tc<<<grid_l, 256, SM_TOTAL>>>(nullptr, nullptr, 0, N, 256, as2, ad2);
    gat_agg<<<N, 128>>>(g2, b2, m2, v2);

    // --- classifier ---
    conv_split_w<<<(nc2 + 255) / 256, 256>>>(Wc, nc2);
    gemm_tc<<<grid_c, 256, SM_TOTAL>>>(bc, out, 1, N, 64, nullptr, nullptr);
}

// round 11
// speedup vs baseline: 2.5095x; 1.1008x over previous
#include <cuda_runtime.h>
#include <cuda_bf16.h>
#include <cstdint>

// ---------------------------------------------------------------------------
// GATModel on GB300: tcgen05 bf16 split-GEMM, 4-stage K pipeline (double
// buffered, cp.async groups) + chunked two-phase GAT aggregate.
// R11: pipelined GEMM; launch order puts gemm_tc 4th so ncu profiles it.
// ---------------------------------------------------------------------------

#if defined(__CUDA_ARCH_FEAT_SM103_ALL) || defined(__CUDA_ARCH_FEAT_SM100_ALL) || \
    defined(__CUDA_ARCH_FEAT_SM101_ALL) || defined(__CUDA_ARCH_SPECIFIC__)
#define TC_OK 1
#else
#define TC_OK 0
#endif

#define NMAX 50000
#define EMAX 500000

__device__ float          g_buf1[NMAX * 256];
__device__ __nv_bfloat16  g_a_hi[NMAX * 256];
__device__ __nv_bfloat16  g_a_lo[NMAX * 256];
__device__ __nv_bfloat16  g_wb_hi[256 * 256];
__device__ __nv_bfloat16  g_wb_lo[256 * 256];
__device__ float g_ssrc[NMAX * 4];
__device__ float g_sdst[NMAX * 4];
__device__ int   g_counts[NMAX];
__device__ int   g_rowbeg[NMAX];
__device__ int   g_rowend[NMAX];
__device__ int   g_cursor[NMAX];
__device__ int   g_csrc[EMAX];
__device__ int   g_is64;
__device__ int   g_total;

// ---------------- edge_index dtype detection ----------------
__global__ void detect_dtype(const void* __restrict__ ei, int N) {
    const long long* p = (const long long*)ei;
    int ok = 1;
    for (int i = 0; i < 16; i++) {
        long long v = p[i];
        if (v < 0 || v >= (long long)N) ok = 0;
    }
    g_is64 = ok;
}
__device__ __forceinline__ int load_idx(const void* ei, long long pos) {
    if (g_is64) return (int)((const long long*)ei)[pos];
    return ((const int*)ei)[pos];
}

// ---------------- CSR build ----------------
__global__ void zero_counts(int N) {
    int i = blockIdx.x * blockDim.x + threadIdx.x;
    if (i < N) g_counts[i] = 0;
    if (i == 0) g_total = 0;
}
__global__ void hist_kernel(const void* __restrict__ ei, int E, int N) {
    int e = blockIdx.x * blockDim.x + threadIdx.x;
    if (e < E) {
        int d = load_idx(ei, (long long)E + e);
        if (d >= 0 && d < N) atomicAdd(&g_counts[d], 1);
    }
}
__global__ void __launch_bounds__(1024)
alloc_rows(int N) {
    __shared__ int sh[1024];
    __shared__ int sbase;
    int tid = threadIdx.x;
    int i = blockIdx.x * 1024 + tid;
    int c = (i < N) ? g_counts[i] : 0;
    sh[tid] = c;
    __syncthreads();
    for (int off = 1; off < 1024; off <<= 1) {
        int v = (tid >= off) ? sh[tid - off] : 0;
        __syncthreads();
        sh[tid] += v;
        __syncthreads();
    }
    if (tid == 1023) sbase = atomicAdd(&g_total, sh[1023]);
    __syncthreads();
    if (i < N) {
        int b = sbase + sh[tid] - c;
        g_rowbeg[i] = b;
        g_rowend[i] = b + c;
        g_cursor[i] = b;
    }
}
__global__ void scatter_kernel(const void* __restrict__ ei, int E, int N) {
    int e = blockIdx.x * blockDim.x + threadIdx.x;
    if (e < E) {
        int d = load_idx(ei, (long long)E + e);
        int s = load_idx(ei, e);
        if (d >= 0 && d < N && s >= 0 && s < N) {
            int pos = atomicAdd(&g_cursor[d], 1);
            if (pos >= 0 && pos < E) g_csrc[pos] = s;
        }
    }
}

// ---------------- fp32 -> bf16 hi/lo split conversions ----------------
__global__ void conv_split_x(const float* __restrict__ src, int n2) {
    int i = blockIdx.x * blockDim.x + threadIdx.x;
    if (i < n2) {
        float2 v = ((const float2*)src)[i];
        __nv_bfloat16 h0 = __float2bfloat16(v.x);
        __nv_bfloat16 h1 = __float2bfloat16(v.y);
        ((__nv_bfloat162*)g_a_hi)[i] = __halves2bfloat162(h0, h1);
        ((__nv_bfloat162*)g_a_lo)[i] = __halves2bfloat162(
            __float2bfloat16(v.x - __bfloat162float(h0)),
            __float2bfloat16(v.y - __bfloat162float(h1)));
    }
}
__global__ void conv_split_w(const float* __restrict__ src, int n2) {
    int i = blockIdx.x * blockDim.x + threadIdx.x;
    if (i < n2) {
        float2 v = ((const float2*)src)[i];
        __nv_bfloat16 h0 = __float2bfloat16(v.x);
        __nv_bfloat16 h1 = __float2bfloat16(v.y);
        ((__nv_bfloat162*)g_wb_hi)[i] = __halves2bfloat162(h0, h1);
        ((__nv_bfloat162*)g_wb_lo)[i] = __halves2bfloat162(
            __float2bfloat16(v.x - __bfloat162float(h0)),
            __float2bfloat16(v.y - __bfloat162float(h1)));
    }
}

// ---------------- tcgen05 helpers (arch-specific pass only) ----------------
#if TC_OK
__device__ __forceinline__ uint32_t elect_one_pred() {
    uint32_t pred;
    asm volatile("{\n\t.reg .pred p;\n\telect.sync _|p, 0xFFFFFFFF;\n\t"
                 "selp.b32 %0, 1, 0, p;\n\t}" : "=r"(pred));
    return pred;
}
__device__ __forceinline__ uint32_t smem_to_u32(const void* p) {
    uint32_t a;
    asm("{ .reg .u64 t; cvta.to.shared.u64 t, %1; cvt.u32.u64 %0, t; }"
        : "=r"(a) : "l"(p));
    return a;
}
#define MBARRIER_INIT(mbar, count) \
    asm volatile("mbarrier.init.shared.b64 [%0], %1;" \
                 :: "r"((uint32_t)(mbar)), "r"((uint32_t)(count)) : "memory")
#define MBARRIER_WAIT_PARITY(mbar, parity) do { \
    uint32_t _m = (uint32_t)(mbar), _p = (uint32_t)(parity), _d; \
    asm volatile("{\n\t.reg .pred p;\n\t" \
        "mbarrier.try_wait.parity.acquire.cta.shared::cta.b64 p, [%1], %2;\n\t" \
        "selp.b32 %0, 1, 0, p;\n\t}" : "=r"(_d) : "r"(_m), "r"(_p) : "memory"); \
    if (!_d) { \
        asm volatile("{\n\t.reg .pred P1;\n\t" \
            "WL_%=:\n\t" \
            "mbarrier.try_wait.parity.acquire.cta.shared::cta.b64 P1, [%0], %1, 0x989680;\n\t" \
            "@P1 bra.uni WD_%=;\n\tbra.uni WL_%=;\n\tWD_%=:\n\t}" \
            :: "r"(_m), "r"(_p) : "memory"); \
    } \
} while (0)
#define TCGEN05_ALLOC(sr, n) \
    asm volatile("tcgen05.alloc.cta_group::1.sync.aligned.shared::cta.b32 [%0], %1;" \
                 :: "r"((uint32_t)(sr)), "r"((uint32_t)(n)) : "memory")
#define TCGEN05_DEALLOC(t, n) \
    asm volatile("tcgen05.dealloc.cta_group::1.sync.aligned.b32 %0, %1;" \
                 :: "r"(t), "r"((uint32_t)(n)))
#define TCGEN05_RELINQ() \
    asm volatile("tcgen05.relinquish_alloc_permit.cta_group::1.sync.aligned;")
#define TCGEN05_COMMIT(mbar) \
    asm volatile("tcgen05.commit.cta_group::1.mbarrier::arrive::one.shared::cluster.b64 [%0];" \
                 :: "r"((uint32_t)(mbar)) : "memory")
#define TCGEN05_FENCE_AFTER() \
    asm volatile("tcgen05.fence::after_thread_sync;" ::: "memory")
#define TCGEN05_WAIT_LD() \
    asm volatile("tcgen05.wait::ld.sync.aligned;" ::: "memory")
#define TCGEN05_LD_32X32B_X32(r, ta) \
    asm volatile("tcgen05.ld.sync.aligned.32x32b.x32.b32 " \
        "{%0, %1, %2, %3, %4, %5, %6, %7, %8, %9, %10, %11, %12, %13, %14, %15, " \
        " %16, %17, %18, %19, %20, %21, %22, %23, %24, %25, %26, %27, %28, %29, %30, %31}, [%32];" \
        : "=r"((r)[0]), "=r"((r)[1]), "=r"((r)[2]), "=r"((r)[3]), \
          "=r"((r)[4]), "=r"((r)[5]), "=r"((r)[6]), "=r"((r)[7]), \
          "=r"((r)[8]), "=r"((r)[9]), "=r"((r)[10]), "=r"((r)[11]), \
          "=r"((r)[12]), "=r"((r)[13]), "=r"((r)[14]), "=r"((r)[15]), \
          "=r"((r)[16]), "=r"((r)[17]), "=r"((r)[18]), "=r"((r)[19]), \
          "=r"((r)[20]), "=r"((r)[21]), "=r"((r)[22]), "=r"((r)[23]), \
          "=r"((r)[24]), "=r"((r)[25]), "=r"((r)[26]), "=r"((r)[27]), \
          "=r"((r)[28]), "=r"((r)[29]), "=r"((r)[30]), "=r"((r)[31]) \
        : "r"(ta))
#define CP_ASYNC16(dst, src) \
    asm volatile("cp.async.cg.shared.global [%0], [%1], 16;" \
                 :: "r"((uint32_t)(dst)), "l"(src) : "memory")
#define CP_COMMIT() \
    asm volatile("cp.async.commit_group;" ::: "memory")
#define CP_WAIT_GROUP(n) \
    asm volatile("cp.async.wait_group %0;" :: "n"(n) : "memory")

__device__ __forceinline__ uint64_t make_desc(uint32_t addr) {
    uint64_t base = (uint64_t(2) << 61) | (uint64_t(1) << 46) |
                    (uint64_t(64) << 32) | (uint64_t(1) << 16);
    return base | ((uint64_t)(addr >> 4) & 0x3FFF);
}
__device__ __forceinline__ void mma_f16_ss(uint32_t d, uint64_t ad, uint64_t bd,
                                           uint32_t idesc, bool en) {
    uint32_t e = en ? 1u : 0u;
    asm volatile("{\n\t.reg .pred p;\n\tsetp.ne.u32 p, %5, 0;\n\t"
                 "tcgen05.mma.cta_group::1.kind::f16 [%0], %1, %2, %3, {%4, %4, %4, %4}, p;\n\t}"
                 :: "r"(d), "l"(ad), "l"(bd), "r"(idesc), "r"(0u), "r"(e)
                 : "memory");
}
#define MMA_IDESC 0x8100490u
#endif  // TC_OK

// ---------------- tcgen05 split-GEMM, 4-stage K pipeline, occ=2 ----------------
// C[128,64] = A[128,256]*B[64,256]^T via 4 K-stages of 64, double-buffered.
// Stage buffer: A_hi 16K | A_lo 16K | B_hi 8K | B_lo 8K = 48K; 2 bufs = 96K.
#define SM_TMEM 0
#define SM_MB0 8
#define SM_MB1 16
#define SM_BUF 1024
#define STG_SZ 49152
#define OFF_ALO 16384
#define OFF_BHI 32768
#define OFF_BLO 40960
#define SM_TOTAL (1024 + 2 * STG_SZ)

__global__ void __launch_bounds__(256)
gemm_tc(const float* __restrict__ bias,
        float* __restrict__ Cext, int toExt, int M, int Nout,
        const float* __restrict__ a_src, const float* __restrict__ a_dst) {
#if TC_OK
    extern __shared__ char smem[];
    uint32_t sb = smem_to_u32(smem);
    int tid = threadIdx.x;
    int wid = tid >> 5;
    int lane = tid & 31;
    int row0 = blockIdx.x * 128;
    int col0 = blockIdx.y * 64;
    float* C = toExt ? Cext : (float*)g_buf1;

    if (wid == 0) {
        TCGEN05_ALLOC(sb + SM_TMEM, 128);
        TCGEN05_RELINQ();
    }
    if (tid == 0) {
        MBARRIER_INIT(sb + SM_MB0, 1);
        MBARRIER_INIT(sb + SM_MB1, 1);
    }
    __syncthreads();
    uint32_t tmem;
    asm volatile("ld.shared.b32 %0, [%1];" : "=r"(tmem) : "r"(sb + SM_TMEM));

    // ---- per-thread load mappings ----
    int ar = tid & 127;
    bool a_hi = tid < 128;
    const __nv_bfloat16* a_srcp =
        (a_hi ? g_a_hi : g_a_lo) + (size_t)(row0 + ar) * 256;
    int a_off_base = (ar >> 3) * 1024 + (ar & 7) * 128;
    int a_sub = a_hi ? 0 : OFF_ALO;
    bool a_ok = (row0 + ar) < M;

    int rb = tid >> 1;
    int br = rb & 63;
    bool b_hi = rb < 64;
    const __nv_bfloat16* b_srcp =
        (b_hi ? g_wb_hi : g_wb_lo) + (size_t)(col0 + br) * 256;
    int b_off_base = (br >> 3) * 1024 + (br & 7) * 128;
    int b_sub = (b_hi ? OFF_BHI : OFF_BLO);
    int b_c0 = (tid & 1) * 4;

    // stage loader: stage s -> buffer s&1
    auto load_stage = [&](int s) {
        uint32_t bufb = sb + SM_BUF + (s & 1) * STG_SZ;
        {   // A: 8 uint4 per thread
            const uint4* src = (const uint4*)(a_srcp + s * 64);
#pragma unroll
            for (int c = 0; c < 8; c++) {
                int off = a_off_base + c * 16;
                off ^= (off >> 3) & 0x70;
                if (a_ok) CP_ASYNC16(bufb + a_sub + off, src + c);
                else *(uint4*)(smem + (bufb - sb) + a_sub + off) =
                         make_uint4(0u, 0u, 0u, 0u);
            }
        }
        {   // B: 4 uint4 per thread
            const uint4* src = (const uint4*)(b_srcp + s * 64);
#pragma unroll
            for (int q = 0; q < 4; q++) {
                int c = b_c0 + q;
                int off = b_off_base + c * 16;
                off ^= (off >> 3) & 0x70;
                CP_ASYNC16(bufb + b_sub + off, src + c);
            }
        }
        CP_COMMIT();
    };

    load_stage(0);
    load_stage(1);

#pragma unroll
    for (int s = 0; s < 4; s++) {
        if (s < 3) CP_WAIT_GROUP(1); else CP_WAIT_GROUP(0);
        __syncthreads();
        asm volatile("fence.proxy.async.shared::cta;" ::: "memory");

        if (wid == 0) {
            if (elect_one_pred()) {
                uint32_t bufb = sb + SM_BUF + (s & 1) * STG_SZ;
                uint64_t dA_hi = make_desc(bufb);
                uint64_t dA_lo = make_desc(bufb + OFF_ALO);
                uint64_t dB_hi = make_desc(bufb + OFF_BHI);
                uint64_t dB_lo = make_desc(bufb + OFF_BLO);
#pragma unroll
                for (int term = 0; term < 3; term++) {
                    uint64_t da = (term == 2) ? dA_lo : dA_hi;
                    uint64_t db = (term == 1) ? dB_lo : dB_hi;
#pragma unroll
                    for (int kc = 0; kc < 4; kc++) {
                        mma_f16_ss(tmem, da + kc * 2, db + kc * 2, MMA_IDESC,
                                   !(s == 0 && term == 0 && kc == 0));
                    }
                }
                TCGEN05_COMMIT(sb + ((s & 1) ? SM_MB1 : SM_MB0));
            }
        }
        if (s < 2) {
            // buffer s&1 is reused by stage s+2: wait for this stage's MMA
            MBARRIER_WAIT_PARITY(sb + ((s & 1) ? SM_MB1 : SM_MB0), 0);
            load_stage(s + 2);
        }
    }

    MBARRIER_WAIT_PARITY(sb + SM_MB0, 1);   // stage 2 done
    MBARRIER_WAIT_PARITY(sb + SM_MB1, 1);   // stage 3 done
    TCGEN05_FENCE_AFTER();

    // ---- epilogue: warps 0-3 read D rows, fp32 C (+bias) + fused scores ----
    if (wid < 4) {
        uint32_t d0[32], d1[32];
        TCGEN05_LD_32X32B_X32(d0, tmem);
        TCGEN05_LD_32X32B_X32(d1, tmem + 32);
        TCGEN05_WAIT_LD();
        int r = row0 + wid * 32 + lane;
        if (r < M) {
            float cv[64];
#pragma unroll
            for (int j = 0; j < 32; j++) {
                cv[j] = __uint_as_float(d0[j]);
                cv[32 + j] = __uint_as_float(d1[j]);
            }
            if (bias) {
#pragma unroll
                for (int j = 0; j < 64; j++) cv[j] += bias[col0 + j];
            }
            float* crow = C + (size_t)r * Nout + col0;
#pragma unroll
            for (int q = 0; q < 16; q++) {
                *(float4*)(crow + q * 4) =
                    make_float4(cv[4 * q], cv[4 * q + 1], cv[4 * q + 2], cv[4 * q + 3]);
            }
            if (a_src) {
                float vs = 0.f, vd = 0.f;
#pragma unroll
                for (int j = 0; j < 64; j++) {
                    vs = fmaf(cv[j], a_src[col0 + j], vs);
                    vd = fmaf(cv[j], a_dst[col0 + j], vd);
                }
                g_ssrc[r * 4 + blockIdx.y] = vs;
                g_sdst[r * 4 + blockIdx.y] = vd;
            }
        }
    }
    __syncthreads();
    if (tid == 0) {
        asm volatile("mbarrier.inval.shared.b64 [%0];" :: "r"(sb + SM_MB0) : "memory");
        asm volatile("mbarrier.inval.shared.b64 [%0];" :: "r"(sb + SM_MB1) : "memory");
    }
    if (wid == 0) TCGEN05_DEALLOC(tmem, 128);
#endif  // TC_OK
}

// ---------------- GAT aggregate + BN + ELU (chunked two-phase) ----------------
__global__ void __launch_bounds__(128)
gat_agg(const float* __restrict__ gamma, const float* __restrict__ beta,
        const float* __restrict__ mean, const float* __restrict__ var) {
    __shared__ float wgt[32][4];
    __shared__ int   sidx[32];
    __shared__ float smax[4];

    int n = blockIdx.x;
    int tid = threadIdx.x;
    int head = tid >> 5;
    int lane = tid & 31;
    int beg = g_rowbeg[n];
    int end = g_rowend[n];
    const float* hfeat = g_buf1;

    {
        float sd_h = g_sdst[n * 4 + head];
        float m = 0.f;
        for (int i = beg + lane; i < end; i += 32) {
            int s = g_csrc[i];
            float e = g_ssrc[s * 4 + head] + sd_h;
            e = (e >= 0.f) ? e : 0.2f * e;
            m = fmaxf(m, e);
        }
#pragma unroll
        for (int o = 16; o; o >>= 1) m = fmaxf(m, __shfl_xor_sync(~0u, m, o));
        if (lane == 0) smax[head] = m;
    }
    __syncthreads();

    int eh = tid & 3;
    int eo = tid >> 2;
    float sd_eh = g_sdst[n * 4 + eh];
    float m_eh = smax[eh];

    float acc0 = 0.f, acc1 = 0.f, ws = 0.f;
    int c = tid * 2;

    for (int base = beg; base < end; base += 32) {
        int cnt = min(32, end - base);
        {
            float w = 0.f;
            int s = -1;
            if (eo < cnt) {
                s = g_csrc[base + eo];
                float e = g_ssrc[s * 4 + eh] + sd_eh;
                e = (e >= 0.f) ? e : 0.2f * e;
                w = __expf(e - m_eh);
            }
            wgt[eo][eh] = w;
            if (eh == 0) sidx[eo] = s;
        }
        __syncthreads();
        for (int j = 0; j < cnt; j++) {
            float w = wgt[j][head];
            ws += w;
            float2 hv = *(const float2*)&hfeat[(size_t)sidx[j] * 256 + c];
            acc0 = fmaf(w, hv.x, acc0);
            acc1 = fmaf(w, hv.y, acc1);
        }
        __syncthreads();
    }

    float inv = 1.f / fmaxf(ws, 1e-9f);
    float o0 = acc0 * inv;
    float o1 = acc1 * inv;

    o0 = (o0 - mean[c]) * rsqrtf(var[c] + 1e-5f) * gamma[c] + beta[c];
    o1 = (o1 - mean[c + 1]) * rsqrtf(var[c + 1] + 1e-5f) * gamma[c + 1] + beta[c + 1];
    o0 = (o0 > 0.f) ? o0 : expm1f(o0);
    o1 = (o1 > 0.f) ? o1 : expm1f(o1);

    __nv_bfloat16 h0 = __float2bfloat16(o0);
    __nv_bfloat16 h1 = __float2bfloat16(o1);
    size_t idx2 = ((size_t)n * 256 + c) >> 1;
    ((__nv_bfloat162*)g_a_hi)[idx2] = __halves2bfloat162(h0, h1);
    ((__nv_bfloat162*)g_a_lo)[idx2] = __halves2bfloat162(
        __float2bfloat16(o0 - __bfloat162float(h0)),
        __float2bfloat16(o1 - __bfloat162float(h1)));
}

// ---------------------------------------------------------------------------
extern "C" void kernel_launch(void* const* d_in, const int* in_sizes, int n_in,
                              void* d_out, int out_size) {
    const float* x   = (const float*)d_in[0];
    const void*  ei  = d_in[1];
    const float* W1  = (const float*)d_in[2];
    const float* as1 = (const float*)d_in[3];
    const float* ad1 = (const float*)d_in[4];
    const float* g1  = (const float*)d_in[5];
    const float* b1  = (const float*)d_in[6];
    const float* m1  = (const float*)d_in[7];
    const float* v1  = (const float*)d_in[8];
    const float* W2  = (const float*)d_in[9];
    const float* as2 = (const float*)d_in[10];
    const float* ad2 = (const float*)d_in[11];
    const float* g2  = (const float*)d_in[12];
    const float* b2  = (const float*)d_in[13];
    const float* m2  = (const float*)d_in[14];
    const float* v2  = (const float*)d_in[15];
    const float* Wc  = (const float*)d_in[16];
    const float* bc  = (const float*)d_in[17];
    float* out = (float*)d_out;

    int N = in_sizes[0] / 256;
    int E = in_sizes[1] / 2;

    cudaFuncSetAttribute(gemm_tc, cudaFuncAttributeMaxDynamicSharedMemorySize,
                         SM_TOTAL);

    dim3 grid_l((N + 127) / 128, 4);
    dim3 grid_c((N + 127) / 128, 1);
    int nx2 = N * 128;
    int nw2 = 256 * 256 / 2;
    int nc2 = 64 * 256 / 2;

    // Launch order puts the layer-1 GEMM 4th: ncu (-s/-c bounded) captures it.
    conv_split_x<<<(nx2 + 255) / 256, 256>>>(x, nx2);              // 1
    conv_split_w<<<(nw2 + 255) / 256, 256>>>(W1, nw2);             // 2
    detect_dtype<<<1, 1>>>(ei, N);                                 // 3
    gemm_tc<<<grid_l, 256, SM_TOTAL>>>(nullptr, nullptr, 0, N, 256, as1, ad1); // 4
    zero_counts<<<(N + 255) / 256, 256>>>(N);                      // 5
    hist_kernel<<<(E + 255) / 256, 256>>>(ei, E, N);               // 6
    alloc_rows<<<(N + 1023) / 1024, 1024>>>(N);                    // 7
    scatter_kernel<<<(E + 255) / 256, 256>>>(ei, E, N);            // 8
    gat_agg<<<N, 128>>>(g1, b1, m1, v1);                           // 9

    // --- layer 2 ---
    conv_split_w<<<(nw2 + 255) / 256, 256>>>(W2, nw2);
    gemm_tc<<<grid_l, 256, SM_TOTAL>>>(nullptr, nullptr, 0, N, 256, as2, ad2);
    gat_agg<<<N, 128>>>(g2, b2, m2, v2);

    // --- classifier ---
    conv_split_w<<<(nc2 + 255) / 256, 256>>>(Wc, nc2);
    gemm_tc<<<grid_c, 256, SM_TOTAL>>>(bc, out, 1, N, 64, nullptr, nullptr);
}